// round 8
// baseline (speedup 1.0000x reference)
#include <cuda_runtime.h>
#include <math.h>
#include <stdint.h>

// ---------------- problem constants ----------------
#define CB   128     // batch
#define CN   49      // spatial tokens
#define CIN  2048    // backbone channels
#define CG   256     // query groups
#define CD   768     // decoder dim
#define CH   8       // heads
#define CHD  96      // head dim
#define CFF  2048    // ffn dim
#define NCLS 12547
#define CDUP 50

// ---------------- scratch (device globals; no allocation allowed) ----------------
__device__ float g_mem  [CB*CN*CD];
__device__ float g_k    [CB*CN*CD];
__device__ float g_v    [CB*CN*CD];
__device__ float g_tln  [CG*CD];
__device__ float g_q    [CG*CD];
__device__ float g_attn [CB*CG*CD];
__device__ float g_oproj[CB*CG*CD];
__device__ float g_t2   [CB*CG*CD];
__device__ float g_ff1  [CB*CG*CFF];
__device__ float g_ff2  [CB*CG*CD];
__device__ float g_h    [CB*CG*CD];

// ============================================================================
// TF32 tensor-core GEMM: C[M,N] = A[M,K] @ B[K,N] + bias[N]  (optional ReLU)
// Requires M%128==0, N%256==0, K%16==0 (true for all calls here).
// 128x256x16 block tile, 256 threads (8 warps, 2x4), warp tile 64x64.
//   -> 8 LDSM.x4 feed 32 mmas per warp-kk-step (219 B L1 traffic per mma,
//      vs 312 B/mma at 32x64 warp tiles) — attacks the 74% L1 ceiling.
// A kept [m][k] (stride 20 floats), B stored TRANSPOSED [n][k] (stride 20);
// both conflict-free for ldmatrix and STS.128. cvt.rna.tf32 at STS time ->
// numerics identical to prior rounds. Double-buffered smem (1 CTA/SM now).
// 61 KB dynamic smem.
// ============================================================================
#define BM 128
#define BN 256
#define BK 16
#define ASTRIDE 20           // floats; 80B rows: 16B aligned, LDSM-conflict-free
#define BTS     20           // BsT [n][k] stride, same property
#define ASZ (BM * ASTRIDE)   // 2560 floats
#define BSZ (BN * BTS)       // 5120 floats
#define GEMM_SMEM_BYTES (2 * (ASZ + BSZ) * 4)   // 61440

__device__ __forceinline__ float to_tf32(float x) {
    asm("cvt.rna.tf32.f32 %0, %0;" : "+f"(x));
    return x;
}

__device__ __forceinline__ void mma1688(float* d, const uint32_t* a, const uint32_t* b) {
    asm volatile(
        "mma.sync.aligned.m16n8k8.row.col.f32.tf32.tf32.f32 "
        "{%0,%1,%2,%3}, {%4,%5,%6,%7}, {%8,%9}, {%0,%1,%2,%3};"
        : "+f"(d[0]), "+f"(d[1]), "+f"(d[2]), "+f"(d[3])
        : "r"(a[0]), "r"(a[1]), "r"(a[2]), "r"(a[3]), "r"(b[0]), "r"(b[1]));
}

__device__ __forceinline__ void ldsm_x4(uint32_t& r0, uint32_t& r1, uint32_t& r2,
                                        uint32_t& r3, uint32_t addr) {
    asm volatile("ldmatrix.sync.aligned.m8n8.x4.shared.b16 {%0,%1,%2,%3}, [%4];"
                 : "=r"(r0), "=r"(r1), "=r"(r2), "=r"(r3) : "r"(addr));
}

template<bool RELU>
__global__ __launch_bounds__(256, 1) void gemm_tf32_kernel(
    const float* __restrict__ A, const float* __restrict__ B,
    const float* __restrict__ bias, float* __restrict__ C,
    int M, int N, int K)
{
    extern __shared__ float dynsmem[];
    float* As0  = dynsmem;                 // [2][ASZ]
    float* BsT0 = dynsmem + 2 * ASZ;       // [2][BSZ]

    const int tid  = threadIdx.x;
    const int lane = tid & 31;
    const int warp = tid >> 5;
    const int wm   = warp & 1;        // 2 warps along M
    const int wn   = warp >> 1;       // 4 warps along N
    const int m0   = blockIdx.y * BM;
    const int n0   = blockIdx.x * BN;
    const int t    = lane & 3;        // 0..3
    const int g    = lane >> 2;       // 0..7

    // ---- A staging (row-major [m][k], float4 along K): rows ar0, ar0+64 ----
    const int ar0 = tid >> 2;             // 0..63
    const int ac0 = (tid & 3) * 4;        // 0,4,8,12
    const float* Ap0 = A + (size_t)(m0 + ar0) * K + ac0;
    const float* Ap1 = A + (size_t)(m0 + ar0 + 64) * K + ac0;

    // ---- B staging (transpose): thread owns column n = tid, all 16 k rows ----
    const int bn = tid;                   // 0..255
    const float* Bp = B + n0 + bn;

    float acc[4][8][4];
    #pragma unroll
    for (int im = 0; im < 4; im++)
        #pragma unroll
        for (int in = 0; in < 8; in++)
            #pragma unroll
            for (int r = 0; r < 4; r++) acc[im][in][r] = 0.f;

    const int warp_m = wm * 64;
    const int warp_n = wn * 64;
    const int nT = K / BK;

    // per-lane ldmatrix address components
    const int a_row0 = warp_m + (lane & 15);                        // im adds 16
    const int b_rowc = warp_n + (lane & 7) + ((lane >> 4) & 1) * 8; // j adds 16
    const int a_koff = (lane >> 4) << 2;                            // 0 or 4
    const int b_koff = ((lane >> 3) & 1) << 2;                      // 0 or 4

    // ---- prologue: tile 0 -> regs -> smem[0]; prefetch tile 1 ----
    float4 ra0 = *(const float4*)Ap0;
    float4 ra1 = *(const float4*)Ap1;
    float4 rb[4];
    #pragma unroll
    for (int j = 0; j < 4; j++) {
        rb[j].x = Bp[(size_t)(j * 4 + 0) * N];
        rb[j].y = Bp[(size_t)(j * 4 + 1) * N];
        rb[j].z = Bp[(size_t)(j * 4 + 2) * N];
        rb[j].w = Bp[(size_t)(j * 4 + 3) * N];
    }
    {
        float4 v;
        v.x = to_tf32(ra0.x); v.y = to_tf32(ra0.y); v.z = to_tf32(ra0.z); v.w = to_tf32(ra0.w);
        *(float4*)&As0[ar0 * ASTRIDE + ac0] = v;
        v.x = to_tf32(ra1.x); v.y = to_tf32(ra1.y); v.z = to_tf32(ra1.z); v.w = to_tf32(ra1.w);
        *(float4*)&As0[(ar0 + 64) * ASTRIDE + ac0] = v;
        #pragma unroll
        for (int j = 0; j < 4; j++) {
            v.x = to_tf32(rb[j].x); v.y = to_tf32(rb[j].y);
            v.z = to_tf32(rb[j].z); v.w = to_tf32(rb[j].w);
            *(float4*)&BsT0[bn * BTS + j * 4] = v;
        }
    }
    if (nT > 1) {
        ra0 = *(const float4*)(Ap0 + BK);
        ra1 = *(const float4*)(Ap1 + BK);
        const float* bp = Bp + (size_t)BK * N;
        #pragma unroll
        for (int j = 0; j < 4; j++) {
            rb[j].x = bp[(size_t)(j * 4 + 0) * N];
            rb[j].y = bp[(size_t)(j * 4 + 1) * N];
            rb[j].z = bp[(size_t)(j * 4 + 2) * N];
            rb[j].w = bp[(size_t)(j * 4 + 3) * N];
        }
    }
    __syncthreads();

    // ---- mainloop: one barrier per iter; STS/LDG overlap mma ----
    for (int it = 0; it < nT; ++it) {
        const int cur = it & 1;

        if (it + 1 < nT) {
            float* as = As0  + (cur ^ 1) * ASZ;
            float* bs = BsT0 + (cur ^ 1) * BSZ;
            float4 v;
            v.x = to_tf32(ra0.x); v.y = to_tf32(ra0.y); v.z = to_tf32(ra0.z); v.w = to_tf32(ra0.w);
            *(float4*)&as[ar0 * ASTRIDE + ac0] = v;
            v.x = to_tf32(ra1.x); v.y = to_tf32(ra1.y); v.z = to_tf32(ra1.z); v.w = to_tf32(ra1.w);
            *(float4*)&as[(ar0 + 64) * ASTRIDE + ac0] = v;
            #pragma unroll
            for (int j = 0; j < 4; j++) {
                v.x = to_tf32(rb[j].x); v.y = to_tf32(rb[j].y);
                v.z = to_tf32(rb[j].z); v.w = to_tf32(rb[j].w);
                *(float4*)&bs[bn * BTS + j * 4] = v;
            }
        }
        if (it + 2 < nT) {
            const int kp = (it + 2) * BK;
            ra0 = *(const float4*)(Ap0 + kp);
            ra1 = *(const float4*)(Ap1 + kp);
            const float* bp = Bp + (size_t)kp * N;
            #pragma unroll
            for (int j = 0; j < 4; j++) {
                rb[j].x = bp[(size_t)(j * 4 + 0) * N];
                rb[j].y = bp[(size_t)(j * 4 + 1) * N];
                rb[j].z = bp[(size_t)(j * 4 + 2) * N];
                rb[j].w = bp[(size_t)(j * 4 + 3) * N];
            }
        }

        const uint32_t as_u = (uint32_t)__cvta_generic_to_shared(As0  + cur * ASZ);
        const uint32_t bs_u = (uint32_t)__cvta_generic_to_shared(BsT0 + cur * BSZ);

        #pragma unroll
        for (int kk = 0; kk < BK; kk += 8) {
            uint32_t af[4][4];
            #pragma unroll
            for (int im = 0; im < 4; im++) {
                uint32_t addr = as_u + ((a_row0 + im * 16) * ASTRIDE + kk + a_koff) * 4;
                ldsm_x4(af[im][0], af[im][1], af[im][2], af[im][3], addr);
            }
            uint32_t bf[8][2];
            #pragma unroll
            for (int j = 0; j < 4; j++) {
                uint32_t addr = bs_u + ((b_rowc + j * 16) * BTS + kk + b_koff) * 4;
                ldsm_x4(bf[2*j][0], bf[2*j][1], bf[2*j+1][0], bf[2*j+1][1], addr);
            }
            #pragma unroll
            for (int im = 0; im < 4; im++)
                #pragma unroll
                for (int in = 0; in < 8; in++)
                    mma1688(acc[im][in], af[im], bf[in]);
        }
        __syncthreads();
    }

    // ---- epilogue: bias (+ReLU), direct to gmem ----
    #pragma unroll
    for (int in = 0; in < 8; in++) {
        const int c0 = n0 + warp_n + in * 8 + t * 2;
        float2 bv = *(const float2*)(bias + c0);
        #pragma unroll
        for (int im = 0; im < 4; im++) {
            const int r0 = m0 + warp_m + im * 16 + g;
            float2 o0, o1;
            o0.x = acc[im][in][0] + bv.x;
            o0.y = acc[im][in][1] + bv.y;
            o1.x = acc[im][in][2] + bv.x;
            o1.y = acc[im][in][3] + bv.y;
            if (RELU) {
                o0.x = fmaxf(o0.x, 0.f); o0.y = fmaxf(o0.y, 0.f);
                o1.x = fmaxf(o1.x, 0.f); o1.y = fmaxf(o1.y, 0.f);
            }
            *(float2*)(C + (size_t)r0 * N + c0)       = o0;
            *(float2*)(C + (size_t)(r0 + 8) * N + c0) = o1;
        }
    }
}

// ============================================================================
// LayerNorm over D=768 with fused residual: out[row] = LN(a[row] + res[row % rowmod])
// ============================================================================
__global__ __launch_bounds__(256) void ln_residual_kernel(
    const float* __restrict__ a, const float* __restrict__ res,
    const float* __restrict__ gamma, const float* __restrict__ beta,
    float* __restrict__ out, int rowmod)
{
    __shared__ float sh[8];
    __shared__ float s_mean, s_rstd;

    const int row = blockIdx.x;
    const int tid = threadIdx.x;
    const float* ar = a   + (size_t)row * CD;
    const float* rr = res + (size_t)(row % rowmod) * CD;

    float x[3];
    #pragma unroll
    for (int i = 0; i < 3; i++) {
        int j = tid + i * 256;
        x[i] = ar[j] + rr[j];
    }

    float s = x[0] + x[1] + x[2];
    #pragma unroll
    for (int o = 16; o > 0; o >>= 1) s += __shfl_down_sync(0xffffffffu, s, o);
    if ((tid & 31) == 0) sh[tid >> 5] = s;
    __syncthreads();
    if (tid < 32) {
        float v = (tid < 8) ? sh[tid] : 0.f;
        #pragma unroll
        for (int o = 4; o > 0; o >>= 1) v += __shfl_down_sync(0xffffffffu, v, o);
        if (tid == 0) s_mean = v * (1.f / CD);
    }
    __syncthreads();
    const float m = s_mean;

    float d2 = 0.f;
    #pragma unroll
    for (int i = 0; i < 3; i++) { float d = x[i] - m; d2 += d * d; }
    #pragma unroll
    for (int o = 16; o > 0; o >>= 1) d2 += __shfl_down_sync(0xffffffffu, d2, o);
    if ((tid & 31) == 0) sh[tid >> 5] = d2;
    __syncthreads();
    if (tid < 32) {
        float v = (tid < 8) ? sh[tid] : 0.f;
        #pragma unroll
        for (int o = 4; o > 0; o >>= 1) v += __shfl_down_sync(0xffffffffu, v, o);
        if (tid == 0) s_rstd = rsqrtf(v * (1.f / CD) + 1e-5f);
    }
    __syncthreads();
    const float rs = s_rstd;

    float* orow = out + (size_t)row * CD;
    #pragma unroll
    for (int i = 0; i < 3; i++) {
        int j = tid + i * 256;
        orow[j] = (x[i] - m) * rs * gamma[j] + beta[j];
    }
}

// ============================================================================
// Cross-attention. q is batch-independent [G, D]. k,v: [B, N, D]. o: [B, G, D].
// ============================================================================
__global__ __launch_bounds__(256) void attn_kernel(
    const float* __restrict__ q, const float* __restrict__ k,
    const float* __restrict__ v, float* __restrict__ o)
{
    const int h = blockIdx.x;
    const int b = blockIdx.y;
    __shared__ float ks[CN][CHD];
    __shared__ float vs[CN][CHD];

    const int tid = threadIdx.x;
    for (int i = tid; i < CN * CHD; i += 256) {
        int n = i / CHD, d = i % CHD;
        size_t gi = (size_t)(b * CN + n) * CD + h * CHD + d;
        ks[n][d] = k[gi];
        vs[n][d] = v[gi];
    }
    __syncthreads();

    const int g = tid;
    float p[CN];
    #pragma unroll
    for (int n = 0; n < CN; n++) p[n] = 0.f;

    const float* qrow = q + (size_t)g * CD + h * CHD;
    for (int dc = 0; dc < CHD; dc += 8) {
        float q8[8];
        #pragma unroll
        for (int j = 0; j < 8; j++) q8[j] = qrow[dc + j];
        #pragma unroll
        for (int n = 0; n < CN; n++) {
            float s = 0.f;
            #pragma unroll
            for (int j = 0; j < 8; j++) s += q8[j] * ks[n][dc + j];
            p[n] += s;
        }
    }

    const float scale = rsqrtf((float)CHD);
    float mx = -1e30f;
    #pragma unroll
    for (int n = 0; n < CN; n++) { p[n] *= scale; mx = fmaxf(mx, p[n]); }
    float sum = 0.f;
    #pragma unroll
    for (int n = 0; n < CN; n++) { p[n] = expf(p[n] - mx); sum += p[n]; }
    const float inv = 1.f / sum;
    #pragma unroll
    for (int n = 0; n < CN; n++) p[n] *= inv;

    float* orow = o + (size_t)(b * CG + g) * CD + h * CHD;
    for (int d = 0; d < CHD; d++) {
        float acc = 0.f;
        #pragma unroll
        for (int n = 0; n < CN; n++) acc += p[n] * vs[n][d];
        orow[d] = acc;
    }
}

// ============================================================================
// GroupFC: logits[b, g*50+f] = h[b,g,:] . Wg[g,:,f] + bg
// 4-batch register blocking (Wg re-read cut 4x).
// ============================================================================
__global__ __launch_bounds__(800) void groupfc_kernel(
    const float* __restrict__ h, const float* __restrict__ Wg,
    const float* __restrict__ bg, float* __restrict__ out)
{
    const int g   = blockIdx.x;
    const int tid = threadIdx.x;
    const int f   = tid % CDUP;
    const int bi  = tid / CDUP;            // 0..15
    const int b0  = blockIdx.y * 64 + bi;  // + {0,16,32,48}

    const float* w  = Wg + (size_t)g * CD * CDUP + f;
    const float* h0 = h + ((size_t)(b0     ) * CG + g) * CD;
    const float* h1 = h + ((size_t)(b0 + 16) * CG + g) * CD;
    const float* h2 = h + ((size_t)(b0 + 32) * CG + g) * CD;
    const float* h3 = h + ((size_t)(b0 + 48) * CG + g) * CD;

    float a0 = 0.f, a1 = 0.f, a2 = 0.f, a3 = 0.f;
    #pragma unroll 4
    for (int d = 0; d < CD; d++) {
        float wv = w[(size_t)d * CDUP];
        a0 += h0[d] * wv;
        a1 += h1[d] * wv;
        a2 += h2[d] * wv;
        a3 += h3[d] * wv;
    }

    const int c = g * CDUP + f;
    if (c < NCLS) {
        const float bb = bg[c];
        out[(size_t)(b0     ) * NCLS + c] = a0 + bb;
        out[(size_t)(b0 + 16) * NCLS + c] = a1 + bb;
        out[(size_t)(b0 + 32) * NCLS + c] = a2 + bb;
        out[(size_t)(b0 + 48) * NCLS + c] = a3 + bb;
    }
}

// ============================================================================
// Orchestration
// ============================================================================
static inline float* sym(const void* s)
{
    void* p = nullptr;
    cudaGetSymbolAddress(&p, s);
    return (float*)p;
}

extern "C" void kernel_launch(void* const* d_in, const int* in_sizes, int n_in,
                              void* d_out, int out_size)
{
    const float* x       = (const float*)d_in[0];
    const float* W_embed = (const float*)d_in[1];
    const float* b_embed = (const float*)d_in[2];
    const float* query   = (const float*)d_in[3];
    const float* Wq = (const float*)d_in[4];  const float* bq = (const float*)d_in[5];
    const float* Wk = (const float*)d_in[6];  const float* bk = (const float*)d_in[7];
    const float* Wv = (const float*)d_in[8];  const float* bv = (const float*)d_in[9];
    const float* Wo = (const float*)d_in[10]; const float* bo = (const float*)d_in[11];
    const float* g1 = (const float*)d_in[12]; const float* be1 = (const float*)d_in[13];
    const float* g2 = (const float*)d_in[14]; const float* be2 = (const float*)d_in[15];
    const float* g3 = (const float*)d_in[16]; const float* be3 = (const float*)d_in[17];
    const float* W1 = (const float*)d_in[18]; const float* b1 = (const float*)d_in[19];
    const float* W2 = (const float*)d_in[20]; const float* b2 = (const float*)d_in[21];
    const float* Wg = (const float*)d_in[22]; const float* bg = (const float*)d_in[23];
    float* out = (float*)d_out;

    float* mem   = sym(g_mem);
    float* kbuf  = sym(g_k);
    float* vbuf  = sym(g_v);
    float* tln   = sym(g_tln);
    float* qbuf  = sym(g_q);
    float* attn  = sym(g_attn);
    float* oproj = sym(g_oproj);
    float* t2    = sym(g_t2);
    float* ff1   = sym(g_ff1);
    float* ff2   = sym(g_ff2);
    float* hbuf  = sym(g_h);

    const int MBN = CB * CN;   // 6272  (= 49 * 128)
    const int MBG = CB * CG;   // 32768

    // allow 61 KB dynamic smem for the GEMM (attribute set is host-side, capture-safe)
    cudaFuncSetAttribute(gemm_tf32_kernel<false>,
                         cudaFuncAttributeMaxDynamicSharedMemorySize, GEMM_SMEM_BYTES);
    cudaFuncSetAttribute(gemm_tf32_kernel<true>,
                         cudaFuncAttributeMaxDynamicSharedMemorySize, GEMM_SMEM_BYTES);

    // 0) batch-independent: tln = LN(2*query); q = tln @ Wq
    ln_residual_kernel<<<CG, 256>>>(query, query, g1, be1, tln, CG);
    gemm_tf32_kernel<false><<<dim3(CD / BN, CG / BM), 256, GEMM_SMEM_BYTES>>>(
        tln, Wq, bq, qbuf, CG, CD, CD);

    // 1) mem = relu(x @ W_embed + b_embed)
    gemm_tf32_kernel<true><<<dim3(CD / BN, MBN / BM), 256, GEMM_SMEM_BYTES>>>(
        x, W_embed, b_embed, mem, MBN, CD, CIN);

    // 2) k, v projections
    gemm_tf32_kernel<false><<<dim3(CD / BN, MBN / BM), 256, GEMM_SMEM_BYTES>>>(
        mem, Wk, bk, kbuf, MBN, CD, CD);
    gemm_tf32_kernel<false><<<dim3(CD / BN, MBN / BM), 256, GEMM_SMEM_BYTES>>>(
        mem, Wv, bv, vbuf, MBN, CD, CD);

    // 3) attention
    attn_kernel<<<dim3(CH, CB), 256>>>(qbuf, kbuf, vbuf, attn);

    // 4) o-projection
    gemm_tf32_kernel<false><<<dim3(CD / BN, MBG / BM), 256, GEMM_SMEM_BYTES>>>(
        attn, Wo, bo, oproj, MBG, CD, CD);

    // 5) t2 = LN(oproj + tln[g])
    ln_residual_kernel<<<MBG, 256>>>(oproj, tln, g2, be2, t2, CG);

    // 6) ff1 = relu(t2 @ W1 + b1)
    gemm_tf32_kernel<true><<<dim3(CFF / BN, MBG / BM), 256, GEMM_SMEM_BYTES>>>(
        t2, W1, b1, ff1, MBG, CFF, CD);

    // 7) ff2 = ff1 @ W2 + b2
    gemm_tf32_kernel<false><<<dim3(CD / BN, MBG / BM), 256, GEMM_SMEM_BYTES>>>(
        ff1, W2, b2, ff2, MBG, CD, CFF);

    // 8) h = LN(ff2 + t2)
    ln_residual_kernel<<<MBG, 256>>>(ff2, t2, g3, be3, hbuf, MBG);

    // 9) GroupFC -> logits
    groupfc_kernel<<<dim3(CG, CB / 64), 16 * CDUP>>>(hbuf, Wg, bg, out);
}

// round 9
// speedup vs baseline: 1.1302x; 1.1302x over previous
#include <cuda_runtime.h>
#include <math.h>
#include <stdint.h>

// ---------------- problem constants ----------------
#define CB   128     // batch
#define CN   49      // spatial tokens
#define CIN  2048    // backbone channels
#define CG   256     // query groups
#define CD   768     // decoder dim
#define CH   8       // heads
#define CHD  96      // head dim
#define CFF  2048    // ffn dim
#define NCLS 12547
#define CDUP 50

// ---------------- scratch (device globals; no allocation allowed) ----------------
__device__ float g_mem  [CB*CN*CD];
__device__ float g_k    [CB*CN*CD];
__device__ float g_v    [CB*CN*CD];
__device__ float g_tln  [CG*CD];
__device__ float g_q    [CG*CD];
__device__ float g_attn [CB*CG*CD];
__device__ float g_oproj[CB*CG*CD];
__device__ float g_t2   [CB*CG*CD];
__device__ float g_ff1  [CB*CG*CFF];
__device__ float g_ff2  [CB*CG*CD];
__device__ float g_h    [CB*CG*CD];

// ============================================================================
// TF32 tensor-core GEMM: C[M,N] = A[M,K] @ B[K,N] + bias[N]  (optional ReLU)
// Requires M%128==0, N%128==0, K%16==0 (true for all calls here).
// 128x128x16 block tile, 128 threads (4 warps, 2x2), warp tile 64x64.
//   -> 8 LDSM.x4 feed 32 mmas per warp-kk-step (0.25 LDSM/mma; R7 was 0.375)
//   -> 2 CTAs/SM (launch_bounds(128,2)) restores cross-CTA latency hiding
//      that R8's 1-CTA/SM config lost (occ 12.4%, issue 22% -> regression).
// A kept [m][k] (stride 20 floats), B stored TRANSPOSED [n][k] (stride 20);
// both conflict-free for ldmatrix and STS.128. cvt.rna.tf32 at STS time ->
// numerics identical to prior rounds. Double-buffered smem (40 KB static).
// ============================================================================
#define BM 128
#define BN 128
#define BK 16
#define ASTRIDE 20           // floats; 80B rows: 16B aligned, LDSM-conflict-free
#define BTS     20           // BsT [n][k] stride, same property
#define ASZ (BM * ASTRIDE)   // 2560 floats
#define BSZ (BN * BTS)       // 2560 floats

__device__ __forceinline__ float to_tf32(float x) {
    asm("cvt.rna.tf32.f32 %0, %0;" : "+f"(x));
    return x;
}

__device__ __forceinline__ void mma1688(float* d, const uint32_t* a, const uint32_t* b) {
    asm volatile(
        "mma.sync.aligned.m16n8k8.row.col.f32.tf32.tf32.f32 "
        "{%0,%1,%2,%3}, {%4,%5,%6,%7}, {%8,%9}, {%0,%1,%2,%3};"
        : "+f"(d[0]), "+f"(d[1]), "+f"(d[2]), "+f"(d[3])
        : "r"(a[0]), "r"(a[1]), "r"(a[2]), "r"(a[3]), "r"(b[0]), "r"(b[1]));
}

__device__ __forceinline__ void ldsm_x4(uint32_t& r0, uint32_t& r1, uint32_t& r2,
                                        uint32_t& r3, uint32_t addr) {
    asm volatile("ldmatrix.sync.aligned.m8n8.x4.shared.b16 {%0,%1,%2,%3}, [%4];"
                 : "=r"(r0), "=r"(r1), "=r"(r2), "=r"(r3) : "r"(addr));
}

template<bool RELU>
__global__ __launch_bounds__(128, 2) void gemm_tf32_kernel(
    const float* __restrict__ A, const float* __restrict__ B,
    const float* __restrict__ bias, float* __restrict__ C,
    int M, int N, int K)
{
    __shared__ float As [2][ASZ];
    __shared__ float BsT[2][BSZ];

    const int tid  = threadIdx.x;
    const int lane = tid & 31;
    const int warp = tid >> 5;       // 0..3
    const int wm   = warp & 1;       // 2 warps along M
    const int wn   = warp >> 1;      // 2 warps along N
    const int m0   = blockIdx.y * BM;
    const int n0   = blockIdx.x * BN;
    const int t    = lane & 3;       // 0..3
    const int g    = lane >> 2;      // 0..7

    // ---- A staging: 4 float4 per thread; i = tid + 128*j -> (row i>>2, col (i&3)*4)
    const int ar = tid >> 2;             // 0..31 (+32*j)
    const int ac = (tid & 3) * 4;        // 0,4,8,12
    const float* ApB = A + (size_t)(m0 + ar) * K + ac;

    // ---- B staging (transpose): thread owns column n = tid, all 16 k rows ----
    const int bn = tid;                  // 0..127
    const float* Bp = B + n0 + bn;

    float acc[4][8][4];
    #pragma unroll
    for (int im = 0; im < 4; im++)
        #pragma unroll
        for (int in = 0; in < 8; in++)
            #pragma unroll
            for (int r = 0; r < 4; r++) acc[im][in][r] = 0.f;

    const int warp_m = wm * 64;
    const int warp_n = wn * 64;
    const int nT = K / BK;

    // per-lane ldmatrix address components
    const int a_row0 = warp_m + (lane & 15);                        // im adds 16
    const int b_rowc = warp_n + (lane & 7) + ((lane >> 4) & 1) * 8; // j adds 16
    const int a_koff = (lane >> 4) << 2;                            // 0 or 4
    const int b_koff = ((lane >> 3) & 1) << 2;                      // 0 or 4

    // ---- prologue: tile 0 -> regs -> smem[0]; prefetch tile 1 ----
    float4 ra[4], rb[4];
    #pragma unroll
    for (int j = 0; j < 4; j++)
        ra[j] = *(const float4*)(ApB + (size_t)(32 * j) * K);
    #pragma unroll
    for (int j = 0; j < 4; j++) {
        rb[j].x = Bp[(size_t)(j * 4 + 0) * N];
        rb[j].y = Bp[(size_t)(j * 4 + 1) * N];
        rb[j].z = Bp[(size_t)(j * 4 + 2) * N];
        rb[j].w = Bp[(size_t)(j * 4 + 3) * N];
    }
    {
        float4 v;
        #pragma unroll
        for (int j = 0; j < 4; j++) {
            v.x = to_tf32(ra[j].x); v.y = to_tf32(ra[j].y);
            v.z = to_tf32(ra[j].z); v.w = to_tf32(ra[j].w);
            *(float4*)&As[0][(ar + 32 * j) * ASTRIDE + ac] = v;
        }
        #pragma unroll
        for (int j = 0; j < 4; j++) {
            v.x = to_tf32(rb[j].x); v.y = to_tf32(rb[j].y);
            v.z = to_tf32(rb[j].z); v.w = to_tf32(rb[j].w);
            *(float4*)&BsT[0][bn * BTS + j * 4] = v;
        }
    }
    if (nT > 1) {
        #pragma unroll
        for (int j = 0; j < 4; j++)
            ra[j] = *(const float4*)(ApB + (size_t)(32 * j) * K + BK);
        const float* bp = Bp + (size_t)BK * N;
        #pragma unroll
        for (int j = 0; j < 4; j++) {
            rb[j].x = bp[(size_t)(j * 4 + 0) * N];
            rb[j].y = bp[(size_t)(j * 4 + 1) * N];
            rb[j].z = bp[(size_t)(j * 4 + 2) * N];
            rb[j].w = bp[(size_t)(j * 4 + 3) * N];
        }
    }
    __syncthreads();

    // ---- mainloop: one barrier per iter; STS/LDG overlap mma ----
    for (int it = 0; it < nT; ++it) {
        const int cur = it & 1;

        if (it + 1 < nT) {
            float* as = As [cur ^ 1];
            float* bs = BsT[cur ^ 1];
            float4 v;
            #pragma unroll
            for (int j = 0; j < 4; j++) {
                v.x = to_tf32(ra[j].x); v.y = to_tf32(ra[j].y);
                v.z = to_tf32(ra[j].z); v.w = to_tf32(ra[j].w);
                *(float4*)&as[(ar + 32 * j) * ASTRIDE + ac] = v;
            }
            #pragma unroll
            for (int j = 0; j < 4; j++) {
                v.x = to_tf32(rb[j].x); v.y = to_tf32(rb[j].y);
                v.z = to_tf32(rb[j].z); v.w = to_tf32(rb[j].w);
                *(float4*)&bs[bn * BTS + j * 4] = v;
            }
        }
        if (it + 2 < nT) {
            const int kp = (it + 2) * BK;
            #pragma unroll
            for (int j = 0; j < 4; j++)
                ra[j] = *(const float4*)(ApB + (size_t)(32 * j) * K + kp);
            const float* bp = Bp + (size_t)kp * N;
            #pragma unroll
            for (int j = 0; j < 4; j++) {
                rb[j].x = bp[(size_t)(j * 4 + 0) * N];
                rb[j].y = bp[(size_t)(j * 4 + 1) * N];
                rb[j].z = bp[(size_t)(j * 4 + 2) * N];
                rb[j].w = bp[(size_t)(j * 4 + 3) * N];
            }
        }

        const uint32_t as_u = (uint32_t)__cvta_generic_to_shared(As [cur]);
        const uint32_t bs_u = (uint32_t)__cvta_generic_to_shared(BsT[cur]);

        #pragma unroll
        for (int kk = 0; kk < BK; kk += 8) {
            uint32_t af[4][4];
            #pragma unroll
            for (int im = 0; im < 4; im++) {
                uint32_t addr = as_u + ((a_row0 + im * 16) * ASTRIDE + kk + a_koff) * 4;
                ldsm_x4(af[im][0], af[im][1], af[im][2], af[im][3], addr);
            }
            uint32_t bf[8][2];
            #pragma unroll
            for (int j = 0; j < 4; j++) {
                uint32_t addr = bs_u + ((b_rowc + j * 16) * BTS + kk + b_koff) * 4;
                ldsm_x4(bf[2*j][0], bf[2*j][1], bf[2*j+1][0], bf[2*j+1][1], addr);
            }
            #pragma unroll
            for (int im = 0; im < 4; im++)
                #pragma unroll
                for (int in = 0; in < 8; in++)
                    mma1688(acc[im][in], af[im], bf[in]);
        }
        __syncthreads();
    }

    // ---- epilogue: bias (+ReLU), direct to gmem ----
    #pragma unroll
    for (int in = 0; in < 8; in++) {
        const int c0 = n0 + warp_n + in * 8 + t * 2;
        float2 bv = *(const float2*)(bias + c0);
        #pragma unroll
        for (int im = 0; im < 4; im++) {
            const int r0 = m0 + warp_m + im * 16 + g;
            float2 o0, o1;
            o0.x = acc[im][in][0] + bv.x;
            o0.y = acc[im][in][1] + bv.y;
            o1.x = acc[im][in][2] + bv.x;
            o1.y = acc[im][in][3] + bv.y;
            if (RELU) {
                o0.x = fmaxf(o0.x, 0.f); o0.y = fmaxf(o0.y, 0.f);
                o1.x = fmaxf(o1.x, 0.f); o1.y = fmaxf(o1.y, 0.f);
            }
            *(float2*)(C + (size_t)r0 * N + c0)       = o0;
            *(float2*)(C + (size_t)(r0 + 8) * N + c0) = o1;
        }
    }
}

// ============================================================================
// LayerNorm over D=768 with fused residual: out[row] = LN(a[row] + res[row % rowmod])
// ============================================================================
__global__ __launch_bounds__(256) void ln_residual_kernel(
    const float* __restrict__ a, const float* __restrict__ res,
    const float* __restrict__ gamma, const float* __restrict__ beta,
    float* __restrict__ out, int rowmod)
{
    __shared__ float sh[8];
    __shared__ float s_mean, s_rstd;

    const int row = blockIdx.x;
    const int tid = threadIdx.x;
    const float* ar = a   + (size_t)row * CD;
    const float* rr = res + (size_t)(row % rowmod) * CD;

    float x[3];
    #pragma unroll
    for (int i = 0; i < 3; i++) {
        int j = tid + i * 256;
        x[i] = ar[j] + rr[j];
    }

    float s = x[0] + x[1] + x[2];
    #pragma unroll
    for (int o = 16; o > 0; o >>= 1) s += __shfl_down_sync(0xffffffffu, s, o);
    if ((tid & 31) == 0) sh[tid >> 5] = s;
    __syncthreads();
    if (tid < 32) {
        float v = (tid < 8) ? sh[tid] : 0.f;
        #pragma unroll
        for (int o = 4; o > 0; o >>= 1) v += __shfl_down_sync(0xffffffffu, v, o);
        if (tid == 0) s_mean = v * (1.f / CD);
    }
    __syncthreads();
    const float m = s_mean;

    float d2 = 0.f;
    #pragma unroll
    for (int i = 0; i < 3; i++) { float d = x[i] - m; d2 += d * d; }
    #pragma unroll
    for (int o = 16; o > 0; o >>= 1) d2 += __shfl_down_sync(0xffffffffu, d2, o);
    if ((tid & 31) == 0) sh[tid >> 5] = d2;
    __syncthreads();
    if (tid < 32) {
        float v = (tid < 8) ? sh[tid] : 0.f;
        #pragma unroll
        for (int o = 4; o > 0; o >>= 1) v += __shfl_down_sync(0xffffffffu, v, o);
        if (tid == 0) s_rstd = rsqrtf(v * (1.f / CD) + 1e-5f);
    }
    __syncthreads();
    const float rs = s_rstd;

    float* orow = out + (size_t)row * CD;
    #pragma unroll
    for (int i = 0; i < 3; i++) {
        int j = tid + i * 256;
        orow[j] = (x[i] - m) * rs * gamma[j] + beta[j];
    }
}

// ============================================================================
// Cross-attention. q is batch-independent [G, D]. k,v: [B, N, D]. o: [B, G, D].
// ============================================================================
__global__ __launch_bounds__(256) void attn_kernel(
    const float* __restrict__ q, const float* __restrict__ k,
    const float* __restrict__ v, float* __restrict__ o)
{
    const int h = blockIdx.x;
    const int b = blockIdx.y;
    __shared__ float ks[CN][CHD];
    __shared__ float vs[CN][CHD];

    const int tid = threadIdx.x;
    for (int i = tid; i < CN * CHD; i += 256) {
        int n = i / CHD, d = i % CHD;
        size_t gi = (size_t)(b * CN + n) * CD + h * CHD + d;
        ks[n][d] = k[gi];
        vs[n][d] = v[gi];
    }
    __syncthreads();

    const int g = tid;
    float p[CN];
    #pragma unroll
    for (int n = 0; n < CN; n++) p[n] = 0.f;

    const float* qrow = q + (size_t)g * CD + h * CHD;
    for (int dc = 0; dc < CHD; dc += 8) {
        float q8[8];
        #pragma unroll
        for (int j = 0; j < 8; j++) q8[j] = qrow[dc + j];
        #pragma unroll
        for (int n = 0; n < CN; n++) {
            float s = 0.f;
            #pragma unroll
            for (int j = 0; j < 8; j++) s += q8[j] * ks[n][dc + j];
            p[n] += s;
        }
    }

    const float scale = rsqrtf((float)CHD);
    float mx = -1e30f;
    #pragma unroll
    for (int n = 0; n < CN; n++) { p[n] *= scale; mx = fmaxf(mx, p[n]); }
    float sum = 0.f;
    #pragma unroll
    for (int n = 0; n < CN; n++) { p[n] = expf(p[n] - mx); sum += p[n]; }
    const float inv = 1.f / sum;
    #pragma unroll
    for (int n = 0; n < CN; n++) p[n] *= inv;

    float* orow = o + (size_t)(b * CG + g) * CD + h * CHD;
    for (int d = 0; d < CHD; d++) {
        float acc = 0.f;
        #pragma unroll
        for (int n = 0; n < CN; n++) acc += p[n] * vs[n][d];
        orow[d] = acc;
    }
}

// ============================================================================
// GroupFC: logits[b, g*50+f] = h[b,g,:] . Wg[g,:,f] + bg
// 4-batch register blocking (Wg re-read cut 4x).
// ============================================================================
__global__ __launch_bounds__(800) void groupfc_kernel(
    const float* __restrict__ h, const float* __restrict__ Wg,
    const float* __restrict__ bg, float* __restrict__ out)
{
    const int g   = blockIdx.x;
    const int tid = threadIdx.x;
    const int f   = tid % CDUP;
    const int bi  = tid / CDUP;            // 0..15
    const int b0  = blockIdx.y * 64 + bi;  // + {0,16,32,48}

    const float* w  = Wg + (size_t)g * CD * CDUP + f;
    const float* h0 = h + ((size_t)(b0     ) * CG + g) * CD;
    const float* h1 = h + ((size_t)(b0 + 16) * CG + g) * CD;
    const float* h2 = h + ((size_t)(b0 + 32) * CG + g) * CD;
    const float* h3 = h + ((size_t)(b0 + 48) * CG + g) * CD;

    float a0 = 0.f, a1 = 0.f, a2 = 0.f, a3 = 0.f;
    #pragma unroll 4
    for (int d = 0; d < CD; d++) {
        float wv = w[(size_t)d * CDUP];
        a0 += h0[d] * wv;
        a1 += h1[d] * wv;
        a2 += h2[d] * wv;
        a3 += h3[d] * wv;
    }

    const int c = g * CDUP + f;
    if (c < NCLS) {
        const float bb = bg[c];
        out[(size_t)(b0     ) * NCLS + c] = a0 + bb;
        out[(size_t)(b0 + 16) * NCLS + c] = a1 + bb;
        out[(size_t)(b0 + 32) * NCLS + c] = a2 + bb;
        out[(size_t)(b0 + 48) * NCLS + c] = a3 + bb;
    }
}

// ============================================================================
// Orchestration
// ============================================================================
static inline float* sym(const void* s)
{
    void* p = nullptr;
    cudaGetSymbolAddress(&p, s);
    return (float*)p;
}

extern "C" void kernel_launch(void* const* d_in, const int* in_sizes, int n_in,
                              void* d_out, int out_size)
{
    const float* x       = (const float*)d_in[0];
    const float* W_embed = (const float*)d_in[1];
    const float* b_embed = (const float*)d_in[2];
    const float* query   = (const float*)d_in[3];
    const float* Wq = (const float*)d_in[4];  const float* bq = (const float*)d_in[5];
    const float* Wk = (const float*)d_in[6];  const float* bk = (const float*)d_in[7];
    const float* Wv = (const float*)d_in[8];  const float* bv = (const float*)d_in[9];
    const float* Wo = (const float*)d_in[10]; const float* bo = (const float*)d_in[11];
    const float* g1 = (const float*)d_in[12]; const float* be1 = (const float*)d_in[13];
    const float* g2 = (const float*)d_in[14]; const float* be2 = (const float*)d_in[15];
    const float* g3 = (const float*)d_in[16]; const float* be3 = (const float*)d_in[17];
    const float* W1 = (const float*)d_in[18]; const float* b1 = (const float*)d_in[19];
    const float* W2 = (const float*)d_in[20]; const float* b2 = (const float*)d_in[21];
    const float* Wg = (const float*)d_in[22]; const float* bg = (const float*)d_in[23];
    float* out = (float*)d_out;

    float* mem   = sym(g_mem);
    float* kbuf  = sym(g_k);
    float* vbuf  = sym(g_v);
    float* tln   = sym(g_tln);
    float* qbuf  = sym(g_q);
    float* attn  = sym(g_attn);
    float* oproj = sym(g_oproj);
    float* t2    = sym(g_t2);
    float* ff1   = sym(g_ff1);
    float* ff2   = sym(g_ff2);
    float* hbuf  = sym(g_h);

    const int MBN = CB * CN;   // 6272  (= 49 * 128)
    const int MBG = CB * CG;   // 32768

    // 0) batch-independent: tln = LN(2*query); q = tln @ Wq
    ln_residual_kernel<<<CG, 256>>>(query, query, g1, be1, tln, CG);
    gemm_tf32_kernel<false><<<dim3(CD / BN, CG / BM), 128>>>(
        tln, Wq, bq, qbuf, CG, CD, CD);

    // 1) mem = relu(x @ W_embed + b_embed)
    gemm_tf32_kernel<true><<<dim3(CD / BN, MBN / BM), 128>>>(
        x, W_embed, b_embed, mem, MBN, CD, CIN);

    // 2) k, v projections
    gemm_tf32_kernel<false><<<dim3(CD / BN, MBN / BM), 128>>>(
        mem, Wk, bk, kbuf, MBN, CD, CD);
    gemm_tf32_kernel<false><<<dim3(CD / BN, MBN / BM), 128>>>(
        mem, Wv, bv, vbuf, MBN, CD, CD);

    // 3) attention
    attn_kernel<<<dim3(CH, CB), 256>>>(qbuf, kbuf, vbuf, attn);

    // 4) o-projection
    gemm_tf32_kernel<false><<<dim3(CD / BN, MBG / BM), 128>>>(
        attn, Wo, bo, oproj, MBG, CD, CD);

    // 5) t2 = LN(oproj + tln[g])
    ln_residual_kernel<<<MBG, 256>>>(oproj, tln, g2, be2, t2, CG);

    // 6) ff1 = relu(t2 @ W1 + b1)
    gemm_tf32_kernel<true><<<dim3(CFF / BN, MBG / BM), 128>>>(
        t2, W1, b1, ff1, MBG, CFF, CD);

    // 7) ff2 = ff1 @ W2 + b2
    gemm_tf32_kernel<false><<<dim3(CD / BN, MBG / BM), 128>>>(
        ff1, W2, b2, ff2, MBG, CD, CFF);

    // 8) h = LN(ff2 + t2)
    ln_residual_kernel<<<MBG, 256>>>(ff2, t2, g3, be3, hbuf, MBG);

    // 9) GroupFC -> logits
    groupfc_kernel<<<dim3(CG, CB / 64), 16 * CDUP>>>(hbuf, Wg, bg, out);
}

// round 11
// speedup vs baseline: 1.2984x; 1.1489x over previous
#include <cuda_runtime.h>
#include <math.h>
#include <stdint.h>

// ---------------- problem constants ----------------
#define CB   128     // batch
#define CN   49      // spatial tokens
#define CIN  2048    // backbone channels
#define CG   256     // query groups
#define CD   768     // decoder dim
#define CH   8       // heads
#define CHD  96      // head dim
#define CFF  2048    // ffn dim
#define NCLS 12547
#define CDUP 50

// ---------------- scratch (device globals; no allocation allowed) ----------------
__device__ float g_mem  [CB*CN*CD];     // rounded (feeds K/V GEMMs)
__device__ float g_k    [CB*CN*CD];
__device__ float g_v    [CB*CN*CD];
__device__ float g_tln  [CG*CD];        // fp32 (residual for LN2)
__device__ float g_tlnr [CG*CD];        // rounded (q-GEMM A)
__device__ float g_q    [CG*CD];
__device__ float g_attn [CB*CG*CD];     // rounded (o-proj A)
__device__ float g_oproj[CB*CG*CD];
__device__ float g_t2   [CB*CG*CD];     // fp32 (residual for LN3)
__device__ float g_t2r  [CB*CG*CD];     // rounded (FFN1 A)
__device__ float g_ff1  [CB*CG*CFF];    // rounded (FFN2 A)
__device__ float g_ff2  [CB*CG*CD];
__device__ float g_h    [CB*CG*CD];
// pre-rounded / pre-transposed operands
__device__ float g_xr   [CB*CN*CIN];    // rounded x
__device__ float g_wembT[CD*CIN];       // W_embed^T [768][2048]
__device__ float g_wqT  [CD*CD];
__device__ float g_wkT  [CD*CD];
__device__ float g_wvT  [CD*CD];
__device__ float g_woT  [CD*CD];
__device__ float g_w1T  [CFF*CD];       // W1^T [2048][768]
__device__ float g_w2T  [CD*CFF];       // W2^T [768][2048]

__device__ __forceinline__ float to_tf32(float x) {
    asm("cvt.rna.tf32.f32 %0, %0;" : "+f"(x));
    return x;
}

// ============================================================================
// TF32 tensor-core GEMM: C[M,N] = A[M,K] @ Bt[N,K]^T + bias[N]
// A and Bt are PRE-ROUNDED to tf32 (rna) by producer kernels -> mainloop has
// zero cvt, zero register staging, zero transpose: pure cp.async.cg (8x16B
// per thread-iter, 4-stage pipeline) + ldmatrix + mma.
// 128x128x16 block tile, 128 threads (4 warps 2x2), warp tile 64x64,
// 2 CTAs/SM. Numerics identical to prior rounds (every mma input = rna(fp32)).
// ============================================================================
#define BM 128
#define BN 128
#define BK 16
#define SPITCH 20            // floats per smem row: 16B aligned, LDSM-conflict-free
#define ASZ (BM * SPITCH)    // 2560 floats per stage
#define BSZ (BN * SPITCH)
#define STAGES 4
#define GEMM_SMEM_BYTES (STAGES * (ASZ + BSZ) * 4)   // 81920

#define CP_ASYNC16(dst, src) \
    asm volatile("cp.async.cg.shared.global [%0], [%1], 16;" :: "r"(dst), "l"(src))
#define CP_COMMIT() asm volatile("cp.async.commit_group;")
#define CP_WAIT2()  asm volatile("cp.async.wait_group 2;")

__device__ __forceinline__ void mma1688(float* d, const uint32_t* a, const uint32_t* b) {
    asm volatile(
        "mma.sync.aligned.m16n8k8.row.col.f32.tf32.tf32.f32 "
        "{%0,%1,%2,%3}, {%4,%5,%6,%7}, {%8,%9}, {%0,%1,%2,%3};"
        : "+f"(d[0]), "+f"(d[1]), "+f"(d[2]), "+f"(d[3])
        : "r"(a[0]), "r"(a[1]), "r"(a[2]), "r"(a[3]), "r"(b[0]), "r"(b[1]));
}

__device__ __forceinline__ void ldsm_x4(uint32_t& r0, uint32_t& r1, uint32_t& r2,
                                        uint32_t& r3, uint32_t addr) {
    asm volatile("ldmatrix.sync.aligned.m8n8.x4.shared.b16 {%0,%1,%2,%3}, [%4];"
                 : "=r"(r0), "=r"(r1), "=r"(r2), "=r"(r3) : "r"(addr));
}

template<bool RELU, bool ROUND>
__global__ __launch_bounds__(128, 2) void gemm_cp_kernel(
    const float* __restrict__ A, const float* __restrict__ Bt,
    const float* __restrict__ bias, float* __restrict__ C,
    int M, int N, int K)
{
    extern __shared__ float sm[];
    const uint32_t smem_u = (uint32_t)__cvta_generic_to_shared(sm);
    const uint32_t as_u0  = smem_u;                       // [STAGES][ASZ]
    const uint32_t bs_u0  = smem_u + STAGES * ASZ * 4;    // [STAGES][BSZ]

    const int tid  = threadIdx.x;
    const int lane = tid & 31;
    const int warp = tid >> 5;       // 0..3
    const int wm   = warp & 1;       // 2 warps along M
    const int wn   = warp >> 1;      // 2 warps along N
    const int m0   = blockIdx.y * BM;
    const int n0   = blockIdx.x * BN;
    const int t    = lane & 3;       // 0..3
    const int g    = lane >> 2;      // 0..7

    // staging: thread handles rows sr+32j (j=0..3), 16B chunk at kc
    const int sr = tid >> 2;              // 0..31
    const int kc = (tid & 3) * 4;         // 0,4,8,12
    const float* Abase = A  + (size_t)(m0 + sr) * K + kc;
    const float* Bbase = Bt + (size_t)(n0 + sr) * K + kc;
    const uint32_t s_off = (sr * SPITCH + kc) * 4;        // byte offset in stage

    const int nT = K / BK;

    float acc[4][8][4];
    #pragma unroll
    for (int im = 0; im < 4; im++)
        #pragma unroll
        for (int in = 0; in < 8; in++)
            #pragma unroll
            for (int r = 0; r < 4; r++) acc[im][in][r] = 0.f;

    const int warp_m = wm * 64;
    const int warp_n = wn * 64;

    // per-lane ldmatrix address components
    const int a_row0 = warp_m + (lane & 15);                        // im adds 16
    const int b_rowc = warp_n + (lane & 7) + ((lane >> 4) & 1) * 8; // j adds 16
    const int a_koff = (lane >> 4) << 2;                            // 0 or 4
    const int b_koff = ((lane >> 3) & 1) << 2;                      // 0 or 4

    // ---- issue helper: stage s loads K-tile kt ----
    auto issue = [&](int stage, int kt) {
        const size_t kofs = (size_t)kt * BK;
        const uint32_t as = as_u0 + stage * ASZ * 4 + s_off;
        const uint32_t bs = bs_u0 + stage * BSZ * 4 + s_off;
        #pragma unroll
        for (int j = 0; j < 4; j++)
            CP_ASYNC16(as + j * 32 * SPITCH * 4, Abase + (size_t)(32 * j) * K + kofs);
        #pragma unroll
        for (int j = 0; j < 4; j++)
            CP_ASYNC16(bs + j * 32 * SPITCH * 4, Bbase + (size_t)(32 * j) * K + kofs);
    };

    // ---- prologue: stages 0..2 in flight ----
    #pragma unroll
    for (int s = 0; s < STAGES - 1; s++) {
        if (s < nT) issue(s, s);
        CP_COMMIT();
    }

    // ---- mainloop ----
    for (int it = 0; it < nT; ++it) {
        CP_WAIT2();              // stage it landed
        __syncthreads();         // visible to all; buffer (it-1)%4 free

        const int pf = it + STAGES - 1;
        if (pf < nT) issue(pf & 3, pf);
        CP_COMMIT();             // always commit (keeps group count invariant)

        const uint32_t as_u = as_u0 + (it & 3) * ASZ * 4;
        const uint32_t bs_u = bs_u0 + (it & 3) * BSZ * 4;

        #pragma unroll
        for (int kk = 0; kk < BK; kk += 8) {
            uint32_t af[4][4];
            #pragma unroll
            for (int im = 0; im < 4; im++) {
                uint32_t addr = as_u + ((a_row0 + im * 16) * SPITCH + kk + a_koff) * 4;
                ldsm_x4(af[im][0], af[im][1], af[im][2], af[im][3], addr);
            }
            uint32_t bf[8][2];
            #pragma unroll
            for (int j = 0; j < 4; j++) {
                uint32_t addr = bs_u + ((b_rowc + j * 16) * SPITCH + kk + b_koff) * 4;
                ldsm_x4(bf[2*j][0], bf[2*j][1], bf[2*j+1][0], bf[2*j+1][1], addr);
            }
            #pragma unroll
            for (int im = 0; im < 4; im++)
                #pragma unroll
                for (int in = 0; in < 8; in++)
                    mma1688(acc[im][in], af[im], bf[in]);
        }
        __syncthreads();
    }

    // ---- epilogue: bias (+ReLU) (+tf32 round for GEMM-consumed outputs) ----
    #pragma unroll
    for (int in = 0; in < 8; in++) {
        const int c0 = n0 + warp_n + in * 8 + t * 2;
        float2 bv = *(const float2*)(bias + c0);
        #pragma unroll
        for (int im = 0; im < 4; im++) {
            const int r0 = m0 + warp_m + im * 16 + g;
            float2 o0, o1;
            o0.x = acc[im][in][0] + bv.x;
            o0.y = acc[im][in][1] + bv.y;
            o1.x = acc[im][in][2] + bv.x;
            o1.y = acc[im][in][3] + bv.y;
            if (RELU) {
                o0.x = fmaxf(o0.x, 0.f); o0.y = fmaxf(o0.y, 0.f);
                o1.x = fmaxf(o1.x, 0.f); o1.y = fmaxf(o1.y, 0.f);
            }
            if (ROUND) {
                o0.x = to_tf32(o0.x); o0.y = to_tf32(o0.y);
                o1.x = to_tf32(o1.x); o1.y = to_tf32(o1.y);
            }
            *(float2*)(C + (size_t)r0 * N + c0)       = o0;
            *(float2*)(C + (size_t)(r0 + 8) * N + c0) = o1;
        }
    }
}

// ============================================================================
// Tiled transpose + tf32 round: in [R][C] -> out [C][R]. R,C % 32 == 0.
// ============================================================================
__global__ __launch_bounds__(256) void transpose_round_kernel(
    const float* __restrict__ in, float* __restrict__ out, int R, int C)
{
    __shared__ float tile[32][33];
    const int tx = threadIdx.x, ty = threadIdx.y;
    const int r0 = blockIdx.y * 32, c0 = blockIdx.x * 32;
    #pragma unroll
    for (int i = 0; i < 4; i++)
        tile[ty + i * 8][tx] = in[(size_t)(r0 + ty + i * 8) * C + c0 + tx];
    __syncthreads();
    #pragma unroll
    for (int i = 0; i < 4; i++)
        out[(size_t)(c0 + ty + i * 8) * R + r0 + tx] = to_tf32(tile[tx][ty + i * 8]);
}

// elementwise tf32 round (float4), n must be %4==0
__global__ __launch_bounds__(256) void round_kernel(
    const float* __restrict__ in, float* __restrict__ out, int n4)
{
    int i = blockIdx.x * 256 + threadIdx.x;
    if (i < n4) {
        float4 v = ((const float4*)in)[i];
        v.x = to_tf32(v.x); v.y = to_tf32(v.y);
        v.z = to_tf32(v.z); v.w = to_tf32(v.w);
        ((float4*)out)[i] = v;
    }
}

// ============================================================================
// LayerNorm over D=768, fused residual: out[row] = LN(a[row] + res[row % rowmod])
// Optionally also writes a tf32-rounded copy (for downstream GEMM A input).
// ============================================================================
__global__ __launch_bounds__(256) void ln_residual_kernel(
    const float* __restrict__ a, const float* __restrict__ res,
    const float* __restrict__ gamma, const float* __restrict__ beta,
    float* __restrict__ out, float* __restrict__ out_r, int rowmod)
{
    __shared__ float sh[8];
    __shared__ float s_mean, s_rstd;

    const int row = blockIdx.x;
    const int tid = threadIdx.x;
    const float* ar = a   + (size_t)row * CD;
    const float* rr = res + (size_t)(row % rowmod) * CD;

    float x[3];
    #pragma unroll
    for (int i = 0; i < 3; i++) {
        int j = tid + i * 256;
        x[i] = ar[j] + rr[j];
    }

    float s = x[0] + x[1] + x[2];
    #pragma unroll
    for (int o = 16; o > 0; o >>= 1) s += __shfl_down_sync(0xffffffffu, s, o);
    if ((tid & 31) == 0) sh[tid >> 5] = s;
    __syncthreads();
    if (tid < 32) {
        float v = (tid < 8) ? sh[tid] : 0.f;
        #pragma unroll
        for (int o = 4; o > 0; o >>= 1) v += __shfl_down_sync(0xffffffffu, v, o);
        if (tid == 0) s_mean = v * (1.f / CD);
    }
    __syncthreads();
    const float m = s_mean;

    float d2 = 0.f;
    #pragma unroll
    for (int i = 0; i < 3; i++) { float d = x[i] - m; d2 += d * d; }
    #pragma unroll
    for (int o = 16; o > 0; o >>= 1) d2 += __shfl_down_sync(0xffffffffu, d2, o);
    if ((tid & 31) == 0) sh[tid >> 5] = d2;
    __syncthreads();
    if (tid < 32) {
        float v = (tid < 8) ? sh[tid] : 0.f;
        #pragma unroll
        for (int o = 4; o > 0; o >>= 1) v += __shfl_down_sync(0xffffffffu, v, o);
        if (tid == 0) s_rstd = rsqrtf(v * (1.f / CD) + 1e-5f);
    }
    __syncthreads();
    const float rs = s_rstd;

    float* orow = out + (size_t)row * CD;
    #pragma unroll
    for (int i = 0; i < 3; i++) {
        int j = tid + i * 256;
        float y = (x[i] - m) * rs * gamma[j] + beta[j];
        orow[j] = y;
        if (out_r) out_r[(size_t)row * CD + j] = to_tf32(y);
    }
}

// ============================================================================
// Cross-attention. q batch-independent [G, D]. k,v: [B, N, D]. o: [B, G, D]
// (stored tf32-rounded -> consumed only by the o-proj GEMM).
// ============================================================================
__global__ __launch_bounds__(256) void attn_kernel(
    const float* __restrict__ q, const float* __restrict__ k,
    const float* __restrict__ v, float* __restrict__ o)
{
    const int h = blockIdx.x;
    const int b = blockIdx.y;
    __shared__ float ks[CN][CHD];
    __shared__ float vs[CN][CHD];

    const int tid = threadIdx.x;
    for (int i = tid; i < CN * CHD; i += 256) {
        int n = i / CHD, d = i % CHD;
        size_t gi = (size_t)(b * CN + n) * CD + h * CHD + d;
        ks[n][d] = k[gi];
        vs[n][d] = v[gi];
    }
    __syncthreads();

    const int g = tid;
    float p[CN];
    #pragma unroll
    for (int n = 0; n < CN; n++) p[n] = 0.f;

    const float* qrow = q + (size_t)g * CD + h * CHD;
    for (int dc = 0; dc < CHD; dc += 8) {
        float q8[8];
        #pragma unroll
        for (int j = 0; j < 8; j++) q8[j] = qrow[dc + j];
        #pragma unroll
        for (int n = 0; n < CN; n++) {
            float s = 0.f;
            #pragma unroll
            for (int j = 0; j < 8; j++) s += q8[j] * ks[n][dc + j];
            p[n] += s;
        }
    }

    const float scale = rsqrtf((float)CHD);
    float mx = -1e30f;
    #pragma unroll
    for (int n = 0; n < CN; n++) { p[n] *= scale; mx = fmaxf(mx, p[n]); }
    float sum = 0.f;
    #pragma unroll
    for (int n = 0; n < CN; n++) { p[n] = expf(p[n] - mx); sum += p[n]; }
    const float inv = 1.f / sum;
    #pragma unroll
    for (int n = 0; n < CN; n++) p[n] *= inv;

    float* orow = o + (size_t)(b * CG + g) * CD + h * CHD;
    for (int d = 0; d < CHD; d++) {
        float acc = 0.f;
        #pragma unroll
        for (int n = 0; n < CN; n++) acc += p[n] * vs[n][d];
        orow[d] = to_tf32(acc);
    }
}

// ============================================================================
// GroupFC: logits[b, g*50+f] = h[b,g,:] . Wg[g,:,f] + bg
// 4-batch register blocking (Wg re-read cut 4x).
// ============================================================================
__global__ __launch_bounds__(800) void groupfc_kernel(
    const float* __restrict__ h, const float* __restrict__ Wg,
    const float* __restrict__ bg, float* __restrict__ out)
{
    const int g   = blockIdx.x;
    const int tid = threadIdx.x;
    const int f   = tid % CDUP;
    const int bi  = tid / CDUP;            // 0..15
    const int b0  = blockIdx.y * 64 + bi;  // + {0,16,32,48}

    const float* w  = Wg + (size_t)g * CD * CDUP + f;
    const float* h0 = h + ((size_t)(b0     ) * CG + g) * CD;
    const float* h1 = h + ((size_t)(b0 + 16) * CG + g) * CD;
    const float* h2 = h + ((size_t)(b0 + 32) * CG + g) * CD;
    const float* h3 = h + ((size_t)(b0 + 48) * CG + g) * CD;

    float a0 = 0.f, a1 = 0.f, a2 = 0.f, a3 = 0.f;
    #pragma unroll 4
    for (int d = 0; d < CD; d++) {
        float wv = w[(size_t)d * CDUP];
        a0 += h0[d] * wv;
        a1 += h1[d] * wv;
        a2 += h2[d] * wv;
        a3 += h3[d] * wv;
    }

    const int c = g * CDUP + f;
    if (c < NCLS) {
        const float bb = bg[c];
        out[(size_t)(b0     ) * NCLS + c] = a0 + bb;
        out[(size_t)(b0 + 16) * NCLS + c] = a1 + bb;
        out[(size_t)(b0 + 32) * NCLS + c] = a2 + bb;
        out[(size_t)(b0 + 48) * NCLS + c] = a3 + bb;
    }
}

// ============================================================================
// Orchestration
// ============================================================================
static inline float* sym(const void* s)
{
    void* p = nullptr;
    cudaGetSymbolAddress(&p, s);
    return (float*)p;
}

extern "C" void kernel_launch(void* const* d_in, const int* in_sizes, int n_in,
                              void* d_out, int out_size)
{
    const float* x       = (const float*)d_in[0];
    const float* W_embed = (const float*)d_in[1];
    const float* b_embed = (const float*)d_in[2];
    const float* query   = (const float*)d_in[3];
    const float* Wq = (const float*)d_in[4];  const float* bq = (const float*)d_in[5];
    const float* Wk = (const float*)d_in[6];  const float* bk = (const float*)d_in[7];
    const float* Wv = (const float*)d_in[8];  const float* bv = (const float*)d_in[9];
    const float* Wo = (const float*)d_in[10]; const float* bo = (const float*)d_in[11];
    const float* g1 = (const float*)d_in[12]; const float* be1 = (const float*)d_in[13];
    const float* g2 = (const float*)d_in[14]; const float* be2 = (const float*)d_in[15];
    const float* g3 = (const float*)d_in[16]; const float* be3 = (const float*)d_in[17];
    const float* W1 = (const float*)d_in[18]; const float* b1 = (const float*)d_in[19];
    const float* W2 = (const float*)d_in[20]; const float* b2 = (const float*)d_in[21];
    const float* Wg = (const float*)d_in[22]; const float* bg = (const float*)d_in[23];
    float* out = (float*)d_out;

    float* mem   = sym(g_mem);
    float* kbuf  = sym(g_k);
    float* vbuf  = sym(g_v);
    float* tln   = sym(g_tln);
    float* tlnr  = sym(g_tlnr);
    float* qbuf  = sym(g_q);
    float* attn  = sym(g_attn);
    float* oproj = sym(g_oproj);
    float* t2    = sym(g_t2);
    float* t2r   = sym(g_t2r);
    float* ff1   = sym(g_ff1);
    float* ff2   = sym(g_ff2);
    float* hbuf  = sym(g_h);
    float* xr    = sym(g_xr);
    float* wembT = sym(g_wembT);
    float* wqT   = sym(g_wqT);
    float* wkT   = sym(g_wkT);
    float* wvT   = sym(g_wvT);
    float* woT   = sym(g_woT);
    float* w1T   = sym(g_w1T);
    float* w2T   = sym(g_w2T);

    const int MBN = CB * CN;   // 6272
    const int MBG = CB * CG;   // 32768

    cudaFuncSetAttribute(gemm_cp_kernel<false, false>,
                         cudaFuncAttributeMaxDynamicSharedMemorySize, GEMM_SMEM_BYTES);
    cudaFuncSetAttribute(gemm_cp_kernel<true, true>,
                         cudaFuncAttributeMaxDynamicSharedMemorySize, GEMM_SMEM_BYTES);

    const dim3 t32x8(32, 8);

    // ---- prep: pre-round x, pre-transpose+round weights (all independent) ----
    round_kernel<<<(CB * CN * CIN / 4 + 255) / 256, 256>>>(x, xr, CB * CN * CIN / 4);
    transpose_round_kernel<<<dim3(CD / 32, CIN / 32), t32x8>>>(W_embed, wembT, CIN, CD);
    transpose_round_kernel<<<dim3(CD / 32, CD / 32), t32x8>>>(Wq, wqT, CD, CD);
    transpose_round_kernel<<<dim3(CD / 32, CD / 32), t32x8>>>(Wk, wkT, CD, CD);
    transpose_round_kernel<<<dim3(CD / 32, CD / 32), t32x8>>>(Wv, wvT, CD, CD);
    transpose_round_kernel<<<dim3(CD / 32, CD / 32), t32x8>>>(Wo, woT, CD, CD);
    transpose_round_kernel<<<dim3(CFF / 32, CD / 32), t32x8>>>(W1, w1T, CD, CFF);
    transpose_round_kernel<<<dim3(CD / 32, CFF / 32), t32x8>>>(W2, w2T, CFF, CD);

    // 0) batch-independent: tln = LN(2*query) (+rounded copy); q = tlnr @ WqT
    ln_residual_kernel<<<CG, 256>>>(query, query, g1, be1, tln, tlnr, CG);
    gemm_cp_kernel<false, false><<<dim3(CD / BN, CG / BM), 128, GEMM_SMEM_BYTES>>>(
        tlnr, wqT, bq, qbuf, CG, CD, CD);

    // 1) mem = relu(xr @ W_embed) (stored rounded -> K/V GEMM A input)
    gemm_cp_kernel<true, true><<<dim3(CD / BN, MBN / BM), 128, GEMM_SMEM_BYTES>>>(
        xr, wembT, b_embed, mem, MBN, CD, CIN);

    // 2) k, v projections (fp32 out, consumed by attention)
    gemm_cp_kernel<false, false><<<dim3(CD / BN, MBN / BM), 128, GEMM_SMEM_BYTES>>>(
        mem, wkT, bk, kbuf, MBN, CD, CD);
    gemm_cp_kernel<false, false><<<dim3(CD / BN, MBN / BM), 128, GEMM_SMEM_BYTES>>>(
        mem, wvT, bv, vbuf, MBN, CD, CD);

    // 3) attention (stores rounded attn -> o-proj A input)
    attn_kernel<<<dim3(CH, CB), 256>>>(qbuf, kbuf, vbuf, attn);

    // 4) o-projection (fp32 out -> LN2)
    gemm_cp_kernel<false, false><<<dim3(CD / BN, MBG / BM), 128, GEMM_SMEM_BYTES>>>(
        attn, woT, bo, oproj, MBG, CD, CD);

    // 5) t2 = LN(oproj + tln[g]) (+rounded copy for FFN1)
    ln_residual_kernel<<<MBG, 256>>>(oproj, tln, g2, be2, t2, t2r, CG);

    // 6) ff1 = relu(t2r @ W1) (stored rounded -> FFN2 A input)
    gemm_cp_kernel<true, true><<<dim3(CFF / BN, MBG / BM), 128, GEMM_SMEM_BYTES>>>(
        t2r, w1T, b1, ff1, MBG, CFF, CD);

    // 7) ff2 = ff1 @ W2 (fp32 out -> LN3)
    gemm_cp_kernel<false, false><<<dim3(CD / BN, MBG / BM), 128, GEMM_SMEM_BYTES>>>(
        ff1, w2T, b2, ff2, MBG, CD, CFF);

    // 8) h = LN(ff2 + t2)  (fp32, GroupFC consumes fp32)
    ln_residual_kernel<<<MBG, 256>>>(ff2, t2, g3, be3, hbuf, nullptr, MBG);

    // 9) GroupFC -> logits
    groupfc_kernel<<<dim3(CG, CB / 64), 16 * CDUP>>>(hbuf, Wg, bg, out);
}

// round 12
// speedup vs baseline: 1.3059x; 1.0058x over previous
#include <cuda_runtime.h>
#include <math.h>
#include <stdint.h>

// ---------------- problem constants ----------------
#define CB   128
#define CN   49
#define CIN  2048
#define CG   256
#define CD   768
#define CH   8
#define CHD  96
#define CFF  2048
#define NCLS 12547
#define CDUP 50

// ---------------- scratch ----------------
__device__ float g_mem  [CB*CN*CD];
__device__ float g_kv   [CB*CN*2*CD];
__device__ float g_bkv  [2*CD];          // packed [bk|bv]
__device__ float g_tln  [CG*CD];
__device__ float g_tlnr [CG*CD];
__device__ float g_q    [CG*CD];
__device__ float g_attn [CB*CG*CD];
__device__ float g_oproj[CB*CG*CD];
__device__ float g_t2   [CB*CG*CD];
__device__ float g_t2r  [CB*CG*CD];
__device__ float g_ff1  [CB*CG*CFF];
__device__ float g_ff2  [CB*CG*CD];
__device__ float g_h    [CB*CG*CD];
__device__ float g_xr   [CB*CN*CIN];
__device__ float g_wembT[CD*CIN];
__device__ float g_wqT  [CD*CD];
__device__ float g_wkvT [2*CD*CD];
__device__ float g_woT  [CD*CD];
__device__ float g_w1T  [CFF*CD];
__device__ float g_w2T  [CD*CFF];

__device__ __forceinline__ float to_tf32(float x) {
    asm("cvt.rna.tf32.f32 %0, %0;" : "+f"(x));
    return x;
}

// ============================================================================
// TF32 GEMM: C[M,N] = A[M,K] @ Bt[N,K]^T + bias[N]. Pre-rounded operands.
// 128x128x16 tile, 128 thr (4 warps 2x2, warp tile 64x64), 2 CTAs/SM,
// 4-stage cp.async pipeline, ONE __syncthreads per K-iter
// (wait -> sync -> issue(it+3) -> compute(it); buffer (it+3)%4 was last
//  read in iter it-1, finished by all warps before this sync).
// ============================================================================
#define BM 128
#define BN 128
#define BK 16
#define SPITCH 20
#define ASZ (BM * SPITCH)
#define BSZ (BN * SPITCH)
#define STAGES 4
#define GEMM_SMEM_BYTES (STAGES * (ASZ + BSZ) * 4)   // 81920

#define CP_ASYNC16(dst, src) \
    asm volatile("cp.async.cg.shared.global [%0], [%1], 16;" :: "r"(dst), "l"(src))
#define CP_COMMIT() asm volatile("cp.async.commit_group;")
#define CP_WAIT2()  asm volatile("cp.async.wait_group 2;")

__device__ __forceinline__ void mma1688(float* d, const uint32_t* a, const uint32_t* b) {
    asm volatile(
        "mma.sync.aligned.m16n8k8.row.col.f32.tf32.tf32.f32 "
        "{%0,%1,%2,%3}, {%4,%5,%6,%7}, {%8,%9}, {%0,%1,%2,%3};"
        : "+f"(d[0]), "+f"(d[1]), "+f"(d[2]), "+f"(d[3])
        : "r"(a[0]), "r"(a[1]), "r"(a[2]), "r"(a[3]), "r"(b[0]), "r"(b[1]));
}

__device__ __forceinline__ void ldsm_x4(uint32_t& r0, uint32_t& r1, uint32_t& r2,
                                        uint32_t& r3, uint32_t addr) {
    asm volatile("ldmatrix.sync.aligned.m8n8.x4.shared.b16 {%0,%1,%2,%3}, [%4];"
                 : "=r"(r0), "=r"(r1), "=r"(r2), "=r"(r3) : "r"(addr));
}

template<bool RELU, bool ROUND>
__global__ __launch_bounds__(128, 2) void gemm_cp_kernel(
    const float* __restrict__ A, const float* __restrict__ Bt,
    const float* __restrict__ bias, float* __restrict__ C,
    int M, int N, int K)
{
    extern __shared__ float sm[];
    const uint32_t smem_u = (uint32_t)__cvta_generic_to_shared(sm);
    const uint32_t as_u0  = smem_u;
    const uint32_t bs_u0  = smem_u + STAGES * ASZ * 4;

    const int tid  = threadIdx.x;
    const int lane = tid & 31;
    const int warp = tid >> 5;
    const int wm   = warp & 1;
    const int wn   = warp >> 1;
    const int m0   = blockIdx.y * BM;
    const int n0   = blockIdx.x * BN;
    const int t    = lane & 3;
    const int g    = lane >> 2;

    const int sr = tid >> 2;
    const int kc = (tid & 3) * 4;
    const float* Abase = A  + (size_t)(m0 + sr) * K + kc;
    const float* Bbase = Bt + (size_t)(n0 + sr) * K + kc;
    const uint32_t s_off = (sr * SPITCH + kc) * 4;

    const int nT = K / BK;

    float acc[4][8][4];
    #pragma unroll
    for (int im = 0; im < 4; im++)
        #pragma unroll
        for (int in = 0; in < 8; in++)
            #pragma unroll
            for (int r = 0; r < 4; r++) acc[im][in][r] = 0.f;

    const int warp_m = wm * 64;
    const int warp_n = wn * 64;

    const int a_row0 = warp_m + (lane & 15);
    const int b_rowc = warp_n + (lane & 7) + ((lane >> 4) & 1) * 8;
    const int a_koff = (lane >> 4) << 2;
    const int b_koff = ((lane >> 3) & 1) << 2;

    auto issue = [&](int stage, int kt) {
        const size_t kofs = (size_t)kt * BK;
        const uint32_t as = as_u0 + stage * ASZ * 4 + s_off;
        const uint32_t bs = bs_u0 + stage * BSZ * 4 + s_off;
        #pragma unroll
        for (int j = 0; j < 4; j++)
            CP_ASYNC16(as + j * 32 * SPITCH * 4, Abase + (size_t)(32 * j) * K + kofs);
        #pragma unroll
        for (int j = 0; j < 4; j++)
            CP_ASYNC16(bs + j * 32 * SPITCH * 4, Bbase + (size_t)(32 * j) * K + kofs);
    };

    #pragma unroll
    for (int s = 0; s < STAGES - 1; s++) {
        if (s < nT) issue(s, s);
        CP_COMMIT();
    }

    for (int it = 0; it < nT; ++it) {
        CP_WAIT2();
        __syncthreads();

        const int pf = it + STAGES - 1;
        if (pf < nT) issue(pf & 3, pf);
        CP_COMMIT();

        const uint32_t as_u = as_u0 + (it & 3) * ASZ * 4;
        const uint32_t bs_u = bs_u0 + (it & 3) * BSZ * 4;

        #pragma unroll
        for (int kk = 0; kk < BK; kk += 8) {
            uint32_t af[4][4];
            #pragma unroll
            for (int im = 0; im < 4; im++) {
                uint32_t addr = as_u + ((a_row0 + im * 16) * SPITCH + kk + a_koff) * 4;
                ldsm_x4(af[im][0], af[im][1], af[im][2], af[im][3], addr);
            }
            uint32_t bf[8][2];
            #pragma unroll
            for (int j = 0; j < 4; j++) {
                uint32_t addr = bs_u + ((b_rowc + j * 16) * SPITCH + kk + b_koff) * 4;
                ldsm_x4(bf[2*j][0], bf[2*j][1], bf[2*j+1][0], bf[2*j+1][1], addr);
            }
            #pragma unroll
            for (int im = 0; im < 4; im++)
                #pragma unroll
                for (int in = 0; in < 8; in++)
                    mma1688(acc[im][in], af[im], bf[in]);
        }
    }

    #pragma unroll
    for (int in = 0; in < 8; in++) {
        const int c0 = n0 + warp_n + in * 8 + t * 2;
        float2 bv = *(const float2*)(bias + c0);
        #pragma unroll
        for (int im = 0; im < 4; im++) {
            const int r0 = m0 + warp_m + im * 16 + g;
            float2 o0, o1;
            o0.x = acc[im][in][0] + bv.x;
            o0.y = acc[im][in][1] + bv.y;
            o1.x = acc[im][in][2] + bv.x;
            o1.y = acc[im][in][3] + bv.y;
            if (RELU) {
                o0.x = fmaxf(o0.x, 0.f); o0.y = fmaxf(o0.y, 0.f);
                o1.x = fmaxf(o1.x, 0.f); o1.y = fmaxf(o1.y, 0.f);
            }
            if (ROUND) {
                o0.x = to_tf32(o0.x); o0.y = to_tf32(o0.y);
                o1.x = to_tf32(o1.x); o1.y = to_tf32(o1.y);
            }
            *(float2*)(C + (size_t)r0 * N + c0)       = o0;
            *(float2*)(C + (size_t)(r0 + 8) * N + c0) = o1;
        }
    }
}

// ---- tiled transpose + tf32 round: in [R][C] -> out [C][R] ----
__global__ __launch_bounds__(256) void transpose_round_kernel(
    const float* __restrict__ in, float* __restrict__ out, int R, int C)
{
    __shared__ float tile[32][33];
    const int tx = threadIdx.x, ty = threadIdx.y;
    const int r0 = blockIdx.y * 32, c0 = blockIdx.x * 32;
    #pragma unroll
    for (int i = 0; i < 4; i++)
        tile[ty + i * 8][tx] = in[(size_t)(r0 + ty + i * 8) * C + c0 + tx];
    __syncthreads();
    #pragma unroll
    for (int i = 0; i < 4; i++)
        out[(size_t)(c0 + ty + i * 8) * R + r0 + tx] = to_tf32(tile[tx][ty + i * 8]);
}

// ---- elementwise tf32 round (float4) ----
__global__ __launch_bounds__(256) void round_kernel(
    const float* __restrict__ in, float* __restrict__ out, int n4)
{
    int i = blockIdx.x * 256 + threadIdx.x;
    if (i < n4) {
        float4 v = ((const float4*)in)[i];
        v.x = to_tf32(v.x); v.y = to_tf32(v.y);
        v.z = to_tf32(v.z); v.w = to_tf32(v.w);
        ((float4*)out)[i] = v;
    }
}

// ---- pack two 768-float biases into one 1536-float buffer ----
__global__ void pack_bias_kernel(const float* __restrict__ a,
                                 const float* __restrict__ b,
                                 float* __restrict__ out)
{
    int i = blockIdx.x * 256 + threadIdx.x;
    if (i < CD) { out[i] = a[i]; out[i + CD] = b[i]; }
}

// ============================================================================
// LayerNorm (float4, 192 thr/row), fused residual, optional rounded copy.
// ============================================================================
__global__ __launch_bounds__(192) void ln_residual_kernel(
    const float* __restrict__ a, const float* __restrict__ res,
    const float* __restrict__ gamma, const float* __restrict__ beta,
    float* __restrict__ out, float* __restrict__ out_r, int rowmod)
{
    __shared__ float sh[6];
    __shared__ float s_mean, s_rstd;

    const int row = blockIdx.x;
    const int tid = threadIdx.x;
    const int wid = tid >> 5;

    const float4* ar = (const float4*)(a   + (size_t)row * CD);
    const float4* rr = (const float4*)(res + (size_t)(row % rowmod) * CD);

    float4 x = ar[tid];
    float4 rv = rr[tid];
    x.x += rv.x; x.y += rv.y; x.z += rv.z; x.w += rv.w;

    float s = x.x + x.y + x.z + x.w;
    #pragma unroll
    for (int o = 16; o > 0; o >>= 1) s += __shfl_down_sync(0xffffffffu, s, o);
    if ((tid & 31) == 0) sh[wid] = s;
    __syncthreads();
    if (tid < 32) {
        float v = (tid < 6) ? sh[tid] : 0.f;
        #pragma unroll
        for (int o = 4; o > 0; o >>= 1) v += __shfl_down_sync(0xffffffffu, v, o);
        if (tid == 0) s_mean = v * (1.f / CD);
    }
    __syncthreads();
    const float m = s_mean;

    float dx = x.x - m, dy = x.y - m, dz = x.z - m, dw = x.w - m;
    float d2 = dx * dx + dy * dy + dz * dz + dw * dw;
    #pragma unroll
    for (int o = 16; o > 0; o >>= 1) d2 += __shfl_down_sync(0xffffffffu, d2, o);
    if ((tid & 31) == 0) sh[wid] = d2;
    __syncthreads();
    if (tid < 32) {
        float v = (tid < 6) ? sh[tid] : 0.f;
        #pragma unroll
        for (int o = 4; o > 0; o >>= 1) v += __shfl_down_sync(0xffffffffu, v, o);
        if (tid == 0) s_rstd = rsqrtf(v * (1.f / CD) + 1e-5f);
    }
    __syncthreads();
    const float rs = s_rstd;

    float4 gv = ((const float4*)gamma)[tid];
    float4 bv = ((const float4*)beta)[tid];
    float4 y;
    y.x = dx * rs * gv.x + bv.x;
    y.y = dy * rs * gv.y + bv.y;
    y.z = dz * rs * gv.z + bv.z;
    y.w = dw * rs * gv.w + bv.w;
    ((float4*)(out + (size_t)row * CD))[tid] = y;
    if (out_r) {
        float4 yr;
        yr.x = to_tf32(y.x); yr.y = to_tf32(y.y);
        yr.z = to_tf32(y.z); yr.w = to_tf32(y.w);
        ((float4*)(out_r + (size_t)row * CD))[tid] = yr;
    }
}

// ============================================================================
// Cross-attention. q [G,D] batch-independent; kv packed [B*N][1536]
// (k cols 0..767, v cols 768..1535). o stored tf32-rounded.
// ============================================================================
__global__ __launch_bounds__(256) void attn_kernel(
    const float* __restrict__ q, const float* __restrict__ kv,
    float* __restrict__ o)
{
    const int h = blockIdx.x;
    const int b = blockIdx.y;
    __shared__ float ks[CN][CHD];
    __shared__ float vs[CN][CHD];

    const int tid = threadIdx.x;
    for (int i = tid; i < CN * CHD; i += 256) {
        int n = i / CHD, d = i % CHD;
        size_t base = (size_t)(b * CN + n) * (2 * CD) + h * CHD + d;
        ks[n][d] = kv[base];
        vs[n][d] = kv[base + CD];
    }
    __syncthreads();

    const int g = tid;
    float p[CN];
    #pragma unroll
    for (int n = 0; n < CN; n++) p[n] = 0.f;

    const float* qrow = q + (size_t)g * CD + h * CHD;
    for (int dc = 0; dc < CHD; dc += 8) {
        float q8[8];
        #pragma unroll
        for (int j = 0; j < 8; j++) q8[j] = qrow[dc + j];
        #pragma unroll
        for (int n = 0; n < CN; n++) {
            float s = 0.f;
            #pragma unroll
            for (int j = 0; j < 8; j++) s += q8[j] * ks[n][dc + j];
            p[n] += s;
        }
    }

    const float scale = rsqrtf((float)CHD);
    float mx = -1e30f;
    #pragma unroll
    for (int n = 0; n < CN; n++) { p[n] *= scale; mx = fmaxf(mx, p[n]); }
    float sum = 0.f;
    #pragma unroll
    for (int n = 0; n < CN; n++) { p[n] = expf(p[n] - mx); sum += p[n]; }
    const float inv = 1.f / sum;
    #pragma unroll
    for (int n = 0; n < CN; n++) p[n] *= inv;

    float* orow = o + (size_t)(b * CG + g) * CD + h * CHD;
    for (int d = 0; d < CHD; d++) {
        float acc = 0.f;
        #pragma unroll
        for (int n = 0; n < CN; n++) acc += p[n] * vs[n][d];
        orow[d] = to_tf32(acc);
    }
}

// ============================================================================
// GroupFC (4-batch register blocking)
// ============================================================================
__global__ __launch_bounds__(800) void groupfc_kernel(
    const float* __restrict__ h, const float* __restrict__ Wg,
    const float* __restrict__ bg, float* __restrict__ out)
{
    const int g   = blockIdx.x;
    const int tid = threadIdx.x;
    const int f   = tid % CDUP;
    const int bi  = tid / CDUP;
    const int b0  = blockIdx.y * 64 + bi;

    const float* w  = Wg + (size_t)g * CD * CDUP + f;
    const float* h0 = h + ((size_t)(b0     ) * CG + g) * CD;
    const float* h1 = h + ((size_t)(b0 + 16) * CG + g) * CD;
    const float* h2 = h + ((size_t)(b0 + 32) * CG + g) * CD;
    const float* h3 = h + ((size_t)(b0 + 48) * CG + g) * CD;

    float a0 = 0.f, a1 = 0.f, a2 = 0.f, a3 = 0.f;
    #pragma unroll 4
    for (int d = 0; d < CD; d++) {
        float wv = w[(size_t)d * CDUP];
        a0 += h0[d] * wv;
        a1 += h1[d] * wv;
        a2 += h2[d] * wv;
        a3 += h3[d] * wv;
    }

    const int c = g * CDUP + f;
    if (c < NCLS) {
        const float bb = bg[c];
        out[(size_t)(b0     ) * NCLS + c] = a0 + bb;
        out[(size_t)(b0 + 16) * NCLS + c] = a1 + bb;
        out[(size_t)(b0 + 32) * NCLS + c] = a2 + bb;
        out[(size_t)(b0 + 48) * NCLS + c] = a3 + bb;
    }
}

// ============================================================================
// Orchestration
// ============================================================================
static inline float* sym(const void* s)
{
    void* p = nullptr;
    cudaGetSymbolAddress(&p, s);
    return (float*)p;
}

extern "C" void kernel_launch(void* const* d_in, const int* in_sizes, int n_in,
                              void* d_out, int out_size)
{
    const float* x       = (const float*)d_in[0];
    const float* W_embed = (const float*)d_in[1];
    const float* b_embed = (const float*)d_in[2];
    const float* query   = (const float*)d_in[3];
    const float* Wq = (const float*)d_in[4];  const float* bq = (const float*)d_in[5];
    const float* Wk = (const float*)d_in[6];  const float* bk = (const float*)d_in[7];
    const float* Wv = (const float*)d_in[8];  const float* bv = (const float*)d_in[9];
    const float* Wo = (const float*)d_in[10]; const float* bo = (const float*)d_in[11];
    const float* g1 = (const float*)d_in[12]; const float* be1 = (const float*)d_in[13];
    const float* g2 = (const float*)d_in[14]; const float* be2 = (const float*)d_in[15];
    const float* g3 = (const float*)d_in[16]; const float* be3 = (const float*)d_in[17];
    const float* W1 = (const float*)d_in[18]; const float* b1 = (const float*)d_in[19];
    const float* W2 = (const float*)d_in[20]; const float* b2 = (const float*)d_in[21];
    const float* Wg = (const float*)d_in[22]; const float* bg = (const float*)d_in[23];
    float* out = (float*)d_out;

    float* mem   = sym(g_mem);
    float* kv    = sym(g_kv);
    float* bkv   = sym(g_bkv);
    float* tln   = sym(g_tln);
    float* tlnr  = sym(g_tlnr);
    float* qbuf  = sym(g_q);
    float* attn  = sym(g_attn);
    float* oproj = sym(g_oproj);
    float* t2    = sym(g_t2);
    float* t2r   = sym(g_t2r);
    float* ff1   = sym(g_ff1);
    float* ff2   = sym(g_ff2);
    float* hbuf  = sym(g_h);
    float* xr    = sym(g_xr);
    float* wembT = sym(g_wembT);
    float* wqT   = sym(g_wqT);
    float* wkvT  = sym(g_wkvT);
    float* woT   = sym(g_woT);
    float* w1T   = sym(g_w1T);
    float* w2T   = sym(g_w2T);

    const int MBN = CB * CN;   // 6272
    const int MBG = CB * CG;   // 32768

    cudaFuncSetAttribute(gemm_cp_kernel<false, false>,
                         cudaFuncAttributeMaxDynamicSharedMemorySize, GEMM_SMEM_BYTES);
    cudaFuncSetAttribute(gemm_cp_kernel<true, true>,
                         cudaFuncAttributeMaxDynamicSharedMemorySize, GEMM_SMEM_BYTES);

    const dim3 t32x8(32, 8);

    // prep ordered so ncu's fixed slot (6th launch) lands on the embed GEMM
    round_kernel<<<(CB * CN * CIN / 4 + 255) / 256, 256>>>(x, xr, CB * CN * CIN / 4);     // 1
    transpose_round_kernel<<<dim3(CD / 32, CIN / 32), t32x8>>>(W_embed, wembT, CIN, CD);  // 2
    transpose_round_kernel<<<dim3(CD / 32, CD / 32), t32x8>>>(Wq, wqT, CD, CD);           // 3
    ln_residual_kernel<<<CG, 192>>>(query, query, g1, be1, tln, tlnr, CG);                // 4
    gemm_cp_kernel<false, false><<<dim3(CD / BN, CG / BM), 128, GEMM_SMEM_BYTES>>>(
        tlnr, wqT, bq, qbuf, CG, CD, CD);                                                 // 5
    gemm_cp_kernel<true, true><<<dim3(CD / BN, MBN / BM), 128, GEMM_SMEM_BYTES>>>(
        xr, wembT, b_embed, mem, MBN, CD, CIN);                                           // 6 (profiled)

    // remaining weight prep + packed KV bias
    transpose_round_kernel<<<dim3(CD / 32, CD / 32), t32x8>>>(Wk, wkvT, CD, CD);
    transpose_round_kernel<<<dim3(CD / 32, CD / 32), t32x8>>>(Wv, wkvT + CD * CD, CD, CD);
    transpose_round_kernel<<<dim3(CD / 32, CD / 32), t32x8>>>(Wo, woT, CD, CD);
    transpose_round_kernel<<<dim3(CFF / 32, CD / 32), t32x8>>>(W1, w1T, CD, CFF);
    transpose_round_kernel<<<dim3(CD / 32, CFF / 32), t32x8>>>(W2, w2T, CFF, CD);
    pack_bias_kernel<<<(CD + 255) / 256, 256>>>(bk, bv, bkv);

    // merged K|V projection: one GEMM, N=1536, packed output
    gemm_cp_kernel<false, false><<<dim3(2 * CD / BN, MBN / BM), 128, GEMM_SMEM_BYTES>>>(
        mem, wkvT, bkv, kv, MBN, 2 * CD, CD);

    // attention
    attn_kernel<<<dim3(CH, CB), 256>>>(qbuf, kv, attn);

    // o-projection
    gemm_cp_kernel<false, false><<<dim3(CD / BN, MBG / BM), 128, GEMM_SMEM_BYTES>>>(
        attn, woT, bo, oproj, MBG, CD, CD);

    // t2 = LN(oproj + tln[g])
    ln_residual_kernel<<<MBG, 192>>>(oproj, tln, g2, be2, t2, t2r, CG);

    // ff1 = relu(t2r @ W1)
    gemm_cp_kernel<true, true><<<dim3(CFF / BN, MBG / BM), 128, GEMM_SMEM_BYTES>>>(
        t2r, w1T, b1, ff1, MBG, CFF, CD);

    // ff2 = ff1 @ W2
    gemm_cp_kernel<false, false><<<dim3(CD / BN, MBG / BM), 128, GEMM_SMEM_BYTES>>>(
        ff1, w2T, b2, ff2, MBG, CD, CFF);

    // h = LN(ff2 + t2)
    ln_residual_kernel<<<MBG, 192>>>(ff2, t2, g3, be3, hbuf, nullptr, MBG);

    // GroupFC -> logits
    groupfc_kernel<<<dim3(CG, CB / 64), 16 * CDUP>>>(hbuf, Wg, bg, out);
}

// round 14
// speedup vs baseline: 1.3558x; 1.0382x over previous
#include <cuda_runtime.h>
#include <math.h>
#include <stdint.h>

// ---------------- problem constants ----------------
#define CB   128
#define CN   49
#define CIN  2048
#define CG   256
#define CD   768
#define CH   8
#define CHD  96
#define CFF  2048
#define NCLS 12547
#define CDUP 50

// ---------------- scratch ----------------
__device__ float g_mem  [CB*CN*CD];
__device__ float g_kv   [CB*CN*2*CD];
__device__ float g_bkv  [2*CD];          // packed [bk|bv]
__device__ float g_tln  [CG*CD];
__device__ float g_tlnr [CG*CD];
__device__ float g_q    [CG*CD];
__device__ float g_attn [CB*CG*CD];
__device__ float g_oproj[CB*CG*CD];
__device__ float g_t2   [CB*CG*CD];
__device__ float g_t2r  [CB*CG*CD];
__device__ float g_ff1  [CB*CG*CFF];
__device__ float g_ff2  [CB*CG*CD];
__device__ float g_h    [CB*CG*CD];
__device__ float g_xr   [CB*CN*CIN];
__device__ float g_wembT[CD*CIN];
__device__ float g_wqT  [CD*CD];
__device__ float g_wkvT [2*CD*CD];
__device__ float g_woT  [CD*CD];
__device__ float g_w1T  [CFF*CD];
__device__ float g_w2T  [CD*CFF];

__device__ __forceinline__ float to_tf32(float x) {
    asm("cvt.rna.tf32.f32 %0, %0;" : "+f"(x));
    return x;
}

// ============================================================================
// TF32 GEMM: C[M,N] = A[M,K] @ Bt[N,K]^T + bias[N]. Pre-rounded operands.
// 128x128x16 tile, 128 thr (4 warps 2x2, warp tile 64x64), 2 CTAs/SM,
// 4-stage cp.async pipeline, ONE __syncthreads per K-iter.
// ============================================================================
#define BM 128
#define BN 128
#define BK 16
#define SPITCH 20
#define ASZ (BM * SPITCH)
#define BSZ (BN * SPITCH)
#define STAGES 4
#define GEMM_SMEM_BYTES (STAGES * (ASZ + BSZ) * 4)   // 81920

#define CP_ASYNC16(dst, src) \
    asm volatile("cp.async.cg.shared.global [%0], [%1], 16;" :: "r"(dst), "l"(src))
#define CP_COMMIT() asm volatile("cp.async.commit_group;")
#define CP_WAIT2()  asm volatile("cp.async.wait_group 2;")

__device__ __forceinline__ void mma1688(float* d, const uint32_t* a, const uint32_t* b) {
    asm volatile(
        "mma.sync.aligned.m16n8k8.row.col.f32.tf32.tf32.f32 "
        "{%0,%1,%2,%3}, {%4,%5,%6,%7}, {%8,%9}, {%0,%1,%2,%3};"
        : "+f"(d[0]), "+f"(d[1]), "+f"(d[2]), "+f"(d[3])
        : "r"(a[0]), "r"(a[1]), "r"(a[2]), "r"(a[3]), "r"(b[0]), "r"(b[1]));
}

__device__ __forceinline__ void ldsm_x4(uint32_t& r0, uint32_t& r1, uint32_t& r2,
                                        uint32_t& r3, uint32_t addr) {
    asm volatile("ldmatrix.sync.aligned.m8n8.x4.shared.b16 {%0,%1,%2,%3}, [%4];"
                 : "=r"(r0), "=r"(r1), "=r"(r2), "=r"(r3) : "r"(addr));
}

template<bool RELU, bool ROUND>
__global__ __launch_bounds__(128, 2) void gemm_cp_kernel(
    const float* __restrict__ A, const float* __restrict__ Bt,
    const float* __restrict__ bias, float* __restrict__ C,
    int M, int N, int K)
{
    extern __shared__ float sm[];
    const uint32_t smem_u = (uint32_t)__cvta_generic_to_shared(sm);
    const uint32_t as_u0  = smem_u;
    const uint32_t bs_u0  = smem_u + STAGES * ASZ * 4;

    const int tid  = threadIdx.x;
    const int lane = tid & 31;
    const int warp = tid >> 5;
    const int wm   = warp & 1;
    const int wn   = warp >> 1;
    const int m0   = blockIdx.y * BM;
    const int n0   = blockIdx.x * BN;
    const int t    = lane & 3;
    const int g    = lane >> 2;

    const int sr = tid >> 2;
    const int kc = (tid & 3) * 4;
    const float* Abase = A  + (size_t)(m0 + sr) * K + kc;
    const float* Bbase = Bt + (size_t)(n0 + sr) * K + kc;
    const uint32_t s_off = (sr * SPITCH + kc) * 4;

    const int nT = K / BK;

    float acc[4][8][4];
    #pragma unroll
    for (int im = 0; im < 4; im++)
        #pragma unroll
        for (int in = 0; in < 8; in++)
            #pragma unroll
            for (int r = 0; r < 4; r++) acc[im][in][r] = 0.f;

    const int warp_m = wm * 64;
    const int warp_n = wn * 64;

    const int a_row0 = warp_m + (lane & 15);
    const int b_rowc = warp_n + (lane & 7) + ((lane >> 4) & 1) * 8;
    const int a_koff = (lane >> 4) << 2;
    const int b_koff = ((lane >> 3) & 1) << 2;

    auto issue = [&](int stage, int kt) {
        const size_t kofs = (size_t)kt * BK;
        const uint32_t as = as_u0 + stage * ASZ * 4 + s_off;
        const uint32_t bs = bs_u0 + stage * BSZ * 4 + s_off;
        #pragma unroll
        for (int j = 0; j < 4; j++)
            CP_ASYNC16(as + j * 32 * SPITCH * 4, Abase + (size_t)(32 * j) * K + kofs);
        #pragma unroll
        for (int j = 0; j < 4; j++)
            CP_ASYNC16(bs + j * 32 * SPITCH * 4, Bbase + (size_t)(32 * j) * K + kofs);
    };

    #pragma unroll
    for (int s = 0; s < STAGES - 1; s++) {
        if (s < nT) issue(s, s);
        CP_COMMIT();
    }

    for (int it = 0; it < nT; ++it) {
        CP_WAIT2();
        __syncthreads();

        const int pf = it + STAGES - 1;
        if (pf < nT) issue(pf & 3, pf);
        CP_COMMIT();

        const uint32_t as_u = as_u0 + (it & 3) * ASZ * 4;
        const uint32_t bs_u = bs_u0 + (it & 3) * BSZ * 4;

        #pragma unroll
        for (int kk = 0; kk < BK; kk += 8) {
            uint32_t af[4][4];
            #pragma unroll
            for (int im = 0; im < 4; im++) {
                uint32_t addr = as_u + ((a_row0 + im * 16) * SPITCH + kk + a_koff) * 4;
                ldsm_x4(af[im][0], af[im][1], af[im][2], af[im][3], addr);
            }
            uint32_t bf[8][2];
            #pragma unroll
            for (int j = 0; j < 4; j++) {
                uint32_t addr = bs_u + ((b_rowc + j * 16) * SPITCH + kk + b_koff) * 4;
                ldsm_x4(bf[2*j][0], bf[2*j][1], bf[2*j+1][0], bf[2*j+1][1], addr);
            }
            #pragma unroll
            for (int im = 0; im < 4; im++)
                #pragma unroll
                for (int in = 0; in < 8; in++)
                    mma1688(acc[im][in], af[im], bf[in]);
        }
    }

    #pragma unroll
    for (int in = 0; in < 8; in++) {
        const int c0 = n0 + warp_n + in * 8 + t * 2;
        float2 bv = *(const float2*)(bias + c0);
        #pragma unroll
        for (int im = 0; im < 4; im++) {
            const int r0 = m0 + warp_m + im * 16 + g;
            float2 o0, o1;
            o0.x = acc[im][in][0] + bv.x;
            o0.y = acc[im][in][1] + bv.y;
            o1.x = acc[im][in][2] + bv.x;
            o1.y = acc[im][in][3] + bv.y;
            if (RELU) {
                o0.x = fmaxf(o0.x, 0.f); o0.y = fmaxf(o0.y, 0.f);
                o1.x = fmaxf(o1.x, 0.f); o1.y = fmaxf(o1.y, 0.f);
            }
            if (ROUND) {
                o0.x = to_tf32(o0.x); o0.y = to_tf32(o0.y);
                o1.x = to_tf32(o1.x); o1.y = to_tf32(o1.y);
            }
            *(float2*)(C + (size_t)r0 * N + c0)       = o0;
            *(float2*)(C + (size_t)(r0 + 8) * N + c0) = o1;
        }
    }
}

// ---- tiled transpose + tf32 round: in [R][C] -> out [C][R] ----
__global__ __launch_bounds__(256) void transpose_round_kernel(
    const float* __restrict__ in, float* __restrict__ out, int R, int C)
{
    __shared__ float tile[32][33];
    const int tx = threadIdx.x, ty = threadIdx.y;
    const int r0 = blockIdx.y * 32, c0 = blockIdx.x * 32;
    #pragma unroll
    for (int i = 0; i < 4; i++)
        tile[ty + i * 8][tx] = in[(size_t)(r0 + ty + i * 8) * C + c0 + tx];
    __syncthreads();
    #pragma unroll
    for (int i = 0; i < 4; i++)
        out[(size_t)(c0 + ty + i * 8) * R + r0 + tx] = to_tf32(tile[tx][ty + i * 8]);
}

// ---- elementwise tf32 round (float4) ----
__global__ __launch_bounds__(256) void round_kernel(
    const float* __restrict__ in, float* __restrict__ out, int n4)
{
    int i = blockIdx.x * 256 + threadIdx.x;
    if (i < n4) {
        float4 v = ((const float4*)in)[i];
        v.x = to_tf32(v.x); v.y = to_tf32(v.y);
        v.z = to_tf32(v.z); v.w = to_tf32(v.w);
        ((float4*)out)[i] = v;
    }
}

// ---- pack two 768-float biases into one 1536-float buffer ----
__global__ void pack_bias_kernel(const float* __restrict__ a,
                                 const float* __restrict__ b,
                                 float* __restrict__ out)
{
    int i = blockIdx.x * 256 + threadIdx.x;
    if (i < CD) { out[i] = a[i]; out[i + CD] = b[i]; }
}

// ============================================================================
// LayerNorm (float4, 192 thr/row), fused residual, optional rounded copy.
// ============================================================================
__global__ __launch_bounds__(192) void ln_residual_kernel(
    const float* __restrict__ a, const float* __restrict__ res,
    const float* __restrict__ gamma, const float* __restrict__ beta,
    float* __restrict__ out, float* __restrict__ out_r, int rowmod)
{
    __shared__ float sh[6];
    __shared__ float s_mean, s_rstd;

    const int row = blockIdx.x;
    const int tid = threadIdx.x;
    const int wid = tid >> 5;

    const float4* ar = (const float4*)(a   + (size_t)row * CD);
    const float4* rr = (const float4*)(res + (size_t)(row % rowmod) * CD);

    float4 x = ar[tid];
    float4 rv = rr[tid];
    x.x += rv.x; x.y += rv.y; x.z += rv.z; x.w += rv.w;

    float s = x.x + x.y + x.z + x.w;
    #pragma unroll
    for (int o = 16; o > 0; o >>= 1) s += __shfl_down_sync(0xffffffffu, s, o);
    if ((tid & 31) == 0) sh[wid] = s;
    __syncthreads();
    if (tid < 32) {
        float v = (tid < 6) ? sh[tid] : 0.f;
        #pragma unroll
        for (int o = 4; o > 0; o >>= 1) v += __shfl_down_sync(0xffffffffu, v, o);
        if (tid == 0) s_mean = v * (1.f / CD);
    }
    __syncthreads();
    const float m = s_mean;

    float dx = x.x - m, dy = x.y - m, dz = x.z - m, dw = x.w - m;
    float d2 = dx * dx + dy * dy + dz * dz + dw * dw;
    #pragma unroll
    for (int o = 16; o > 0; o >>= 1) d2 += __shfl_down_sync(0xffffffffu, d2, o);
    if ((tid & 31) == 0) sh[wid] = d2;
    __syncthreads();
    if (tid < 32) {
        float v = (tid < 6) ? sh[tid] : 0.f;
        #pragma unroll
        for (int o = 4; o > 0; o >>= 1) v += __shfl_down_sync(0xffffffffu, v, o);
        if (tid == 0) s_rstd = rsqrtf(v * (1.f / CD) + 1e-5f);
    }
    __syncthreads();
    const float rs = s_rstd;

    float4 gv = ((const float4*)gamma)[tid];
    float4 bv = ((const float4*)beta)[tid];
    float4 y;
    y.x = dx * rs * gv.x + bv.x;
    y.y = dy * rs * gv.y + bv.y;
    y.z = dz * rs * gv.z + bv.z;
    y.w = dw * rs * gv.w + bv.w;
    ((float4*)(out + (size_t)row * CD))[tid] = y;
    if (out_r) {
        float4 yr;
        yr.x = to_tf32(y.x); yr.y = to_tf32(y.y);
        yr.z = to_tf32(y.z); yr.w = to_tf32(y.w);
        ((float4*)(out_r + (size_t)row * CD))[tid] = yr;
    }
}

// ============================================================================
// Cross-attention, two-phase with COALESCED output writes.
// q [G,D] batch-independent; kv packed [B*N][1536]. o stored tf32-rounded.
// Phase 1: thread g computes 49 scores + softmax (registers), dumps p -> smem.
// Phase 2: warp owns 32 groups; lanes sweep d -> 128B coalesced stores.
// Accumulation order identical to previous rounds -> bit-identical output.
// Dynamic smem: ks+vs+ps = 18816+18816+51200 = 88832 B.
// ============================================================================
#define ATTN_SMEM_BYTES (CN*CHD*4 * 2 + CG*(CN+1)*4)   // 88832

__global__ __launch_bounds__(256) void attn_kernel(
    const float* __restrict__ q, const float* __restrict__ kv,
    float* __restrict__ o)
{
    extern __shared__ float asm_[];
    float (*ks)[CHD]    = (float(*)[CHD])asm_;                       // [CN][CHD]
    float (*vs)[CHD]    = (float(*)[CHD])(asm_ + CN * CHD);          // [CN][CHD]
    float (*ps)[CN + 1] = (float(*)[CN + 1])(asm_ + 2 * CN * CHD);   // [CG][50]

    const int h = blockIdx.x;
    const int b = blockIdx.y;
    const int tid = threadIdx.x;

    for (int i = tid; i < CN * CHD; i += 256) {
        int n = i / CHD, d = i % CHD;
        size_t base = (size_t)(b * CN + n) * (2 * CD) + h * CHD + d;
        ks[n][d] = kv[base];
        vs[n][d] = kv[base + CD];
    }
    __syncthreads();

    // ---- phase 1: scores + softmax for group g = tid ----
    {
        const int g = tid;
        float p[CN];
        #pragma unroll
        for (int n = 0; n < CN; n++) p[n] = 0.f;

        const float* qrow = q + (size_t)g * CD + h * CHD;
        for (int dc = 0; dc < CHD; dc += 8) {
            float q8[8];
            #pragma unroll
            for (int j = 0; j < 8; j++) q8[j] = qrow[dc + j];
            #pragma unroll
            for (int n = 0; n < CN; n++) {
                float s = 0.f;
                #pragma unroll
                for (int j = 0; j < 8; j++) s += q8[j] * ks[n][dc + j];
                p[n] += s;
            }
        }

        const float scale = rsqrtf((float)CHD);
        float mx = -1e30f;
        #pragma unroll
        for (int n = 0; n < CN; n++) { p[n] *= scale; mx = fmaxf(mx, p[n]); }
        float sum = 0.f;
        #pragma unroll
        for (int n = 0; n < CN; n++) { p[n] = expf(p[n] - mx); sum += p[n]; }
        const float inv = 1.f / sum;
        #pragma unroll
        for (int n = 0; n < CN; n++) ps[g][n] = p[n] * inv;
    }
    __syncthreads();

    // ---- phase 2: o[g][d] = sum_n ps[g][n] * vs[n][d], lanes over d ----
    const int warp = tid >> 5;
    const int lane = tid & 31;
    for (int gg = 0; gg < 32; gg++) {
        const int g = warp * 32 + gg;
        float* orow = o + (size_t)(b * CG + g) * CD + h * CHD;
        const float* pg = ps[g];
        #pragma unroll
        for (int dc = 0; dc < 3; dc++) {
            const int d = dc * 32 + lane;
            float acc = 0.f;
            #pragma unroll
            for (int n = 0; n < CN; n++) acc += pg[n] * vs[n][d];
            orow[d] = to_tf32(acc);
        }
    }
}

// ============================================================================
// GroupFC (4-batch register blocking)
// ============================================================================
__global__ __launch_bounds__(800) void groupfc_kernel(
    const float* __restrict__ h, const float* __restrict__ Wg,
    const float* __restrict__ bg, float* __restrict__ out)
{
    const int g   = blockIdx.x;
    const int tid = threadIdx.x;
    const int f   = tid % CDUP;
    const int bi  = tid / CDUP;
    const int b0  = blockIdx.y * 64 + bi;

    const float* w  = Wg + (size_t)g * CD * CDUP + f;
    const float* h0 = h + ((size_t)(b0     ) * CG + g) * CD;
    const float* h1 = h + ((size_t)(b0 + 16) * CG + g) * CD;
    const float* h2 = h + ((size_t)(b0 + 32) * CG + g) * CD;
    const float* h3 = h + ((size_t)(b0 + 48) * CG + g) * CD;

    float a0 = 0.f, a1 = 0.f, a2 = 0.f, a3 = 0.f;
    #pragma unroll 4
    for (int d = 0; d < CD; d++) {
        float wv = w[(size_t)d * CDUP];
        a0 += h0[d] * wv;
        a1 += h1[d] * wv;
        a2 += h2[d] * wv;
        a3 += h3[d] * wv;
    }

    const int c = g * CDUP + f;
    if (c < NCLS) {
        const float bb = bg[c];
        out[(size_t)(b0     ) * NCLS + c] = a0 + bb;
        out[(size_t)(b0 + 16) * NCLS + c] = a1 + bb;
        out[(size_t)(b0 + 32) * NCLS + c] = a2 + bb;
        out[(size_t)(b0 + 48) * NCLS + c] = a3 + bb;
    }
}

// ============================================================================
// Orchestration
// ============================================================================
static inline float* sym(const void* s)
{
    void* p = nullptr;
    cudaGetSymbolAddress(&p, s);
    return (float*)p;
}

extern "C" void kernel_launch(void* const* d_in, const int* in_sizes, int n_in,
                              void* d_out, int out_size)
{
    const float* x       = (const float*)d_in[0];
    const float* W_embed = (const float*)d_in[1];
    const float* b_embed = (const float*)d_in[2];
    const float* query   = (const float*)d_in[3];
    const float* Wq = (const float*)d_in[4];  const float* bq = (const float*)d_in[5];
    const float* Wk = (const float*)d_in[6];  const float* bk = (const float*)d_in[7];
    const float* Wv = (const float*)d_in[8];  const float* bv = (const float*)d_in[9];
    const float* Wo = (const float*)d_in[10]; const float* bo = (const float*)d_in[11];
    const float* g1 = (const float*)d_in[12]; const float* be1 = (const float*)d_in[13];
    const float* g2 = (const float*)d_in[14]; const float* be2 = (const float*)d_in[15];
    const float* g3 = (const float*)d_in[16]; const float* be3 = (const float*)d_in[17];
    const float* W1 = (const float*)d_in[18]; const float* b1 = (const float*)d_in[19];
    const float* W2 = (const float*)d_in[20]; const float* b2 = (const float*)d_in[21];
    const float* Wg = (const float*)d_in[22]; const float* bg = (const float*)d_in[23];
    float* out = (float*)d_out;

    float* mem   = sym(g_mem);
    float* kv    = sym(g_kv);
    float* bkv   = sym(g_bkv);
    float* tln   = sym(g_tln);
    float* tlnr  = sym(g_tlnr);
    float* qbuf  = sym(g_q);
    float* attn  = sym(g_attn);
    float* oproj = sym(g_oproj);
    float* t2    = sym(g_t2);
    float* t2r   = sym(g_t2r);
    float* ff1   = sym(g_ff1);
    float* ff2   = sym(g_ff2);
    float* hbuf  = sym(g_h);
    float* xr    = sym(g_xr);
    float* wembT = sym(g_wembT);
    float* wqT   = sym(g_wqT);
    float* wkvT  = sym(g_wkvT);
    float* woT   = sym(g_woT);
    float* w1T   = sym(g_w1T);
    float* w2T   = sym(g_w2T);

    const int MBN = CB * CN;   // 6272
    const int MBG = CB * CG;   // 32768

    cudaFuncSetAttribute(gemm_cp_kernel<false, false>,
                         cudaFuncAttributeMaxDynamicSharedMemorySize, GEMM_SMEM_BYTES);
    cudaFuncSetAttribute(gemm_cp_kernel<true, true>,
                         cudaFuncAttributeMaxDynamicSharedMemorySize, GEMM_SMEM_BYTES);
    cudaFuncSetAttribute(attn_kernel,
                         cudaFuncAttributeMaxDynamicSharedMemorySize, ATTN_SMEM_BYTES);

    const dim3 t32x8(32, 8);

    // prep ordered so ncu's fixed profiling slot lands on a big GEMM
    round_kernel<<<(CB * CN * CIN / 4 + 255) / 256, 256>>>(x, xr, CB * CN * CIN / 4);     // 1
    transpose_round_kernel<<<dim3(CD / 32, CIN / 32), t32x8>>>(W_embed, wembT, CIN, CD);  // 2
    transpose_round_kernel<<<dim3(CD / 32, CD / 32), t32x8>>>(Wq, wqT, CD, CD);           // 3
    ln_residual_kernel<<<CG, 192>>>(query, query, g1, be1, tln, tlnr, CG);                // 4
    gemm_cp_kernel<false, false><<<dim3(CD / BN, CG / BM), 128, GEMM_SMEM_BYTES>>>(
        tlnr, wqT, bq, qbuf, CG, CD, CD);                                                 // 5
    gemm_cp_kernel<true, true><<<dim3(CD / BN, MBN / BM), 128, GEMM_SMEM_BYTES>>>(
        xr, wembT, b_embed, mem, MBN, CD, CIN);                                           // 6

    // remaining weight prep + packed KV bias
    transpose_round_kernel<<<dim3(CD / 32, CD / 32), t32x8>>>(Wk, wkvT, CD, CD);
    transpose_round_kernel<<<dim3(CD / 32, CD / 32), t32x8>>>(Wv, wkvT + CD * CD, CD, CD);
    transpose_round_kernel<<<dim3(CD / 32, CD / 32), t32x8>>>(Wo, woT, CD, CD);
    transpose_round_kernel<<<dim3(CFF / 32, CD / 32), t32x8>>>(W1, w1T, CD, CFF);
    transpose_round_kernel<<<dim3(CD / 32, CFF / 32), t32x8>>>(W2, w2T, CFF, CD);
    pack_bias_kernel<<<(CD + 255) / 256, 256>>>(bk, bv, bkv);

    // merged K|V projection: one GEMM, N=1536, packed output
    gemm_cp_kernel<false, false><<<dim3(2 * CD / BN, MBN / BM), 128, GEMM_SMEM_BYTES>>>(
        mem, wkvT, bkv, kv, MBN, 2 * CD, CD);

    // attention (coalesced writes)
    attn_kernel<<<dim3(CH, CB), 256, ATTN_SMEM_BYTES>>>(qbuf, kv, attn);

    // o-projection
    gemm_cp_kernel<false, false><<<dim3(CD / BN, MBG / BM), 128, GEMM_SMEM_BYTES>>>(
        attn, woT, bo, oproj, MBG, CD, CD);

    // t2 = LN(oproj + tln[g])
    ln_residual_kernel<<<MBG, 192>>>(oproj, tln, g2, be2, t2, t2r, CG);

    // ff1 = relu(t2r @ W1)
    gemm_cp_kernel<true, true><<<dim3(CFF / BN, MBG / BM), 128, GEMM_SMEM_BYTES>>>(
        t2r, w1T, b1, ff1, MBG, CFF, CD);

    // ff2 = ff1 @ W2
    gemm_cp_kernel<false, false><<<dim3(CD / BN, MBG / BM), 128, GEMM_SMEM_BYTES>>>(
        ff1, w2T, b2, ff2, MBG, CD, CFF);

    // h = LN(ff2 + t2)
    ln_residual_kernel<<<MBG, 192>>>(ff2, t2, g3, be3, hbuf, nullptr, MBG);

    // GroupFC -> logits
    groupfc_kernel<<<dim3(CG, CB / 64), 16 * CDUP>>>(hbuf, Wg, bg, out);
}